// round 13
// baseline (speedup 1.0000x reference)
#include <cuda_runtime.h>
#include <cuda_fp16.h>
#include <math.h>
#include <stdint.h>

#define DIMC   4096
#define NH     32
#define NKV    8
#define DH     128
#define BB     2
#define TSEQ   2048
#define BT     (BB * TSEQ)
#define QKVN   6144
#define KOFF   4096
#define VOFF   5120
#define KVDIM  1024

__device__ float  g_QKV[BT * QKVN];
__device__ __half g_Xh [BT * DIMC];
__device__ __half g_Wh [DIMC * QKVN];
__device__ __half g_Woh[DIMC * DIMC];
__device__ __half g_Oh [BT * DIMC];
__device__ __half g_Khi[BT * KVDIM];
__device__ __half g_Klo[BT * KVDIM];
__device__ __half g_Vhi[BT * KVDIM];
__device__ __half g_Vlo[BT * KVDIM];
__device__ float  g_cos[TSEQ * 64];
__device__ float  g_sin[TSEQ * 64];

// ---------------- helpers ----------------
__device__ __forceinline__ void mma_f16(float* c, const uint32_t* a, const uint32_t* b) {
    asm volatile(
        "mma.sync.aligned.m16n8k16.row.col.f32.f16.f16.f32 "
        "{%0,%1,%2,%3}, {%4,%5,%6,%7}, {%8,%9}, {%0,%1,%2,%3};"
        : "+f"(c[0]), "+f"(c[1]), "+f"(c[2]), "+f"(c[3])
        : "r"(a[0]), "r"(a[1]), "r"(a[2]), "r"(a[3]), "r"(b[0]), "r"(b[1]));
}
__device__ __forceinline__ void cpasync16(uint32_t dst, const void* src) {
    asm volatile("cp.async.cg.shared.global [%0], [%1], 16;" :: "r"(dst), "l"(src));
}
__device__ __forceinline__ void ldsm_x4(uint32_t* r, uint32_t addr) {
    asm volatile("ldmatrix.sync.aligned.m8n8.x4.shared.b16 {%0,%1,%2,%3}, [%4];"
                 : "=r"(r[0]), "=r"(r[1]), "=r"(r[2]), "=r"(r[3]) : "r"(addr));
}
__device__ __forceinline__ void ldsm_x4_t(uint32_t* r, uint32_t addr) {
    asm volatile("ldmatrix.sync.aligned.m8n8.x4.trans.shared.b16 {%0,%1,%2,%3}, [%4];"
                 : "=r"(r[0]), "=r"(r[1]), "=r"(r[2]), "=r"(r[3]) : "r"(addr));
}
__device__ __forceinline__ void split2(float a, float b, uint32_t& hi, uint32_t& lo) {
    __half ha = __float2half_rn(a), hb = __float2half_rn(b);
    __half la = __float2half_rn(a - __half2float(ha));
    __half lb = __float2half_rn(b - __half2float(hb));
    __half2 H = __halves2half2(ha, hb), L = __halves2half2(la, lb);
    hi = *(uint32_t*)&H; lo = *(uint32_t*)&L;
}

__global__ void pack_w(const float* __restrict__ src, __half* __restrict__ dst,
                       int w, int coff, int dstr, int n4) {
    int i = blockIdx.x * 256 + threadIdx.x;
    if (i >= n4) return;
    int idx = i * 4;
    int r = idx / w, c = idx % w;
    float4 v = *(const float4*)(src + idx);
    __half2* p = (__half2*)(dst + (long)r * dstr + coff + c);
    p[0] = __floats2half2_rn(v.x, v.y);
    p[1] = __floats2half2_rn(v.z, v.w);
}

__global__ void split_kv(int n4) {
    int i = blockIdx.x * 256 + threadIdx.x;
    if (i >= n4) return;
    int idx = i * 4;
    int bt = idx >> 10;
    int c  = idx & 1023;
    float4 k4 = *(const float4*)(g_QKV + (long)bt * QKVN + KOFF + c);
    float4 v4 = *(const float4*)(g_QKV + (long)bt * QKVN + VOFF + c);
    uint32_t h01, l01, h23, l23;
    long o = (long)bt * KVDIM + c;
    split2(k4.x, k4.y, h01, l01); split2(k4.z, k4.w, h23, l23);
    *(uint2*)&g_Khi[o] = make_uint2(h01, h23);
    *(uint2*)&g_Klo[o] = make_uint2(l01, l23);
    split2(v4.x, v4.y, h01, l01); split2(v4.z, v4.w, h23, l23);
    *(uint2*)&g_Vhi[o] = make_uint2(h01, h23);
    *(uint2*)&g_Vlo[o] = make_uint2(l01, l23);
}

// =====================================================================
// FP16 GEMM v2: C[M,N](f32) = A(f16) @ B(f16).
// CTA tile 128x256, BK=32, 256 threads (8 warps), warp tile 64x64.
// cp.async double buffer; ldmatrix A (x4) + B (x4.trans).
// Per-element k accumulation order identical to v1 -> bit-identical C.
// =====================================================================
#define GBK   32
#define ASTR  40      // halves (80 B row)
#define BSTR2 264     // halves (528 B row; 528 % 128 == 16 -> conflict-free ldsm)
#define GEMM_SMEM_BYTES ((2 * 128 * ASTR + 2 * GBK * BSTR2) * 2)   // 54272

__global__ __launch_bounds__(256) void gemm_f16(const __half* __restrict__ A,
                                                const __half* __restrict__ B,
                                                float* __restrict__ C,
                                                int M, int N, int K) {
    extern __shared__ __half hsm[];
    __half* As = hsm;                       // [2][128][ASTR]
    __half* Bs = hsm + 2 * 128 * ASTR;      // [2][GBK][BSTR2]

    const int tid  = threadIdx.x;
    const int brow = blockIdx.y * 128;
    const int bcol = blockIdx.x * 256;
    const int wid  = tid >> 5, lane = tid & 31;
    const int g    = lane >> 2, t = lane & 3;
    const int m_base = (wid & 1) * 64;
    const int n_base = (wid >> 1) * 64;

    // loaders (16B chunks)
    const int a_r = tid >> 2;               // 0..63, +64
    const int a_c = (tid & 3) * 8;
    const int b_r = tid >> 5;               // 0..7, +8*i (i<4)
    const int b_c = (tid & 31) * 8;

    // ldmatrix lane maps
    const int xr8 = lane & 15;
    const int xc8 = (lane >> 4) * 8;
    const int bkr = (lane & 7) + ((lane >> 3) & 1) * 8;   // k row within 16
    const uint32_t sAb = (uint32_t)__cvta_generic_to_shared(As);
    const uint32_t sBb = (uint32_t)__cvta_generic_to_shared(Bs);
    uint32_t aoff[4];
#pragma unroll
    for (int mi = 0; mi < 4; mi++)
        aoff[mi] = ((m_base + 16 * mi + xr8) * ASTR + xc8) * 2;
    uint32_t boff[4];
#pragma unroll
    for (int nj = 0; nj < 4; nj++)
        boff[nj] = (bkr * BSTR2 + n_base + nj * 16 + xc8) * 2;

    float c[4][8][4];
#pragma unroll
    for (int mi = 0; mi < 4; mi++)
#pragma unroll
        for (int ni = 0; ni < 8; ni++)
#pragma unroll
            for (int r = 0; r < 4; r++) c[mi][ni][r] = 0.f;

    const int KT = K / GBK;
    {
#pragma unroll
        for (int i = 0; i < 2; i++) {
            int r = a_r + 64 * i;
            cpasync16((uint32_t)__cvta_generic_to_shared(&As[r * ASTR + a_c]),
                      A + (long)(brow + r) * K + a_c);
        }
#pragma unroll
        for (int i = 0; i < 4; i++) {
            int r = b_r + 8 * i;
            cpasync16((uint32_t)__cvta_generic_to_shared(&Bs[r * BSTR2 + b_c]),
                      B + (long)r * N + bcol + b_c);
        }
        asm volatile("cp.async.commit_group;");
    }

    int s = 0;
    for (int kt = 0; kt < KT; kt++) {
        if (kt + 1 < KT) {
            const int k0 = (kt + 1) * GBK;
            __half* as = As + (s ^ 1) * 128 * ASTR;
            __half* bs = Bs + (s ^ 1) * GBK * BSTR2;
#pragma unroll
            for (int i = 0; i < 2; i++) {
                int r = a_r + 64 * i;
                cpasync16((uint32_t)__cvta_generic_to_shared(&as[r * ASTR + a_c]),
                          A + (long)(brow + r) * K + k0 + a_c);
            }
#pragma unroll
            for (int i = 0; i < 4; i++) {
                int r = b_r + 8 * i;
                cpasync16((uint32_t)__cvta_generic_to_shared(&bs[r * BSTR2 + b_c]),
                          B + (long)(k0 + r) * N + bcol + b_c);
            }
            asm volatile("cp.async.commit_group;");
            asm volatile("cp.async.wait_group 1;");
        } else {
            asm volatile("cp.async.wait_group 0;");
        }
        __syncthreads();

        const uint32_t ab = sAb + (uint32_t)(s * 128 * ASTR * 2);
        const uint32_t bb = sBb + (uint32_t)(s * GBK * BSTR2 * 2);
#pragma unroll
        for (int j = 0; j < 2; j++) {           // two k16 steps
            uint32_t af[4][4], bq[4][4];
#pragma unroll
            for (int mi = 0; mi < 4; mi++)
                ldsm_x4(af[mi], ab + aoff[mi] + j * 32);
#pragma unroll
            for (int nj = 0; nj < 4; nj++)
                ldsm_x4_t(bq[nj], bb + boff[nj] + j * 16 * BSTR2 * 2);
#pragma unroll
            for (int mi = 0; mi < 4; mi++)
#pragma unroll
                for (int nj = 0; nj < 4; nj++) {
                    mma_f16(c[mi][2 * nj + 0], af[mi], &bq[nj][0]);
                    mma_f16(c[mi][2 * nj + 1], af[mi], &bq[nj][2]);
                }
        }
        __syncthreads();
        s ^= 1;
    }

#pragma unroll
    for (int mi = 0; mi < 4; mi++) {
#pragma unroll
        for (int ni = 0; ni < 8; ni++) {
            long row = brow + m_base + 16 * mi + g;
            int  col = bcol + n_base + 8 * ni + 2 * t;
            *(float2*)&C[row * N + col]       = make_float2(c[mi][ni][0], c[mi][ni][1]);
            *(float2*)&C[(row + 8) * N + col] = make_float2(c[mi][ni][2], c[mi][ni][3]);
        }
    }
}

// =====================================================================
// RoPE
// =====================================================================
__global__ void rope_table() {
    int idx = blockIdx.x * 256 + threadIdx.x;
    if (idx >= TSEQ * 64) return;
    int d = idx & 63, t = idx >> 6;
    double inv = pow(10000.0, -(double)d / 64.0);
    double ang = (double)t * inv;
    g_cos[idx] = (float)cos(ang);
    g_sin[idx] = (float)sin(ang);
}

__global__ void rope_apply2(float* __restrict__ x, int nheads, int stride, int hoff, int total) {
    int idx = blockIdx.x * 256 + threadIdx.x;
    if (idx >= total) return;
    int d  = idx & 63;
    int r  = idx >> 6;
    int h  = r % nheads;
    int bt = r / nheads;
    int t  = bt % TSEQ;
    long base = (long)bt * stride + hoff + h * 128 + d;
    float c = g_cos[t * 64 + d], s = g_sin[t * 64 + d];
    float x1 = x[base], x2 = x[base + 64];
    x[base]      = x1 * c - x2 * s;
    x[base + 64] = x1 * s + x2 * c;
}

// =====================================================================
// Flash attention v3 (R12) + longest-first CTA ordering.
// =====================================================================
#define KSTR 136
#define VSTR 136
#define PSTR 72
#define PLN   (64 * KSTR)
#define BUFH  (4 * PLN)
#define PHI_H (2 * BUFH)
#define PLO_H (PHI_H + 128 * PSTR)
#define FLASH_BYTES ((PLO_H + 128 * PSTR) * 2)

__global__ __launch_bounds__(256, 1) void flash_tc() {
    extern __shared__ __half hs[];
    __half* Phi = hs + PHI_H;
    __half* Plo = hs + PLO_H;

    const int tid = threadIdx.x;
    const int qt  = (int)(gridDim.x - 1 - blockIdx.x);   // longest work first
    const int bh  = blockIdx.y;
    const int b   = bh >> 5;
    const int h   = bh & 31;
    const int kvh = h >> 2;
    const int q0  = qt * 128;
    const int lane = tid & 31, wid = tid >> 5;
    const int g = lane >> 2, t = lane & 3;
    const int wm = wid;
    const int r0 = wm * 16 + g;

    const uint32_t smb = (uint32_t)__cvta_generic_to_shared(hs);
    const int n_loc  = (lane & 7) + ((lane >> 4) << 3);
    const int k_half = (lane >> 3) & 1;
    uint32_t koff_rel[4];
#pragma unroll
    for (int j = 0; j < 4; j++)
        koff_rel[j] = ((j * 16 + n_loc) * KSTR + k_half * 8) * 2;
    const int xr  = lane & 15;
    const int xc8 = (lane >> 4) * 8;
    const uint32_t phoff = (PHI_H + (wm * 16 + xr) * PSTR + xc8) * 2;
    const uint32_t ploff = (PLO_H + (wm * 16 + xr) * PSTR + xc8) * 2;
    const int xrv = (lane & 7) + ((lane >> 3) & 1) * 8;
    uint32_t voff_rel[8];
#pragma unroll
    for (int vj = 0; vj < 8; vj++)
        voff_rel[vj] = (xrv * VSTR + vj * 16 + xc8) * 2;

    const float scale = 0.0883883476483184f;
    uint32_t qhi[8][4], qlo[8][4];
    {
        const float* Qg = g_QKV + ((long)(b * TSEQ + q0)) * QKVN + h * DH;
#pragma unroll
        for (int kk = 0; kk < 8; kk++) {
            const int c = kk * 16 + 2 * t;
            float2 a0 = *(const float2*)&Qg[(long)r0 * QKVN + c];
            float2 a1 = *(const float2*)&Qg[(long)(r0 + 8) * QKVN + c];
            float2 a2 = *(const float2*)&Qg[(long)r0 * QKVN + c + 8];
            float2 a3 = *(const float2*)&Qg[(long)(r0 + 8) * QKVN + c + 8];
            split2(a0.x * scale, a0.y * scale, qhi[kk][0], qlo[kk][0]);
            split2(a1.x * scale, a1.y * scale, qhi[kk][1], qlo[kk][1]);
            split2(a2.x * scale, a2.y * scale, qhi[kk][2], qlo[kk][2]);
            split2(a3.x * scale, a3.y * scale, qhi[kk][3], qlo[kk][3]);
        }
    }
    float m0 = -1e30f, m1 = -1e30f, l0 = 0.f, l1 = 0.f;

    const __half* Kh = g_Khi + (long)(b * TSEQ) * KVDIM + kvh * DH;
    const __half* Kl = g_Klo + (long)(b * TSEQ) * KVDIM + kvh * DH;
    const __half* Vh = g_Vhi + (long)(b * TSEQ) * KVDIM + kvh * DH;
    const __half* Vl = g_Vlo + (long)(b * TSEQ) * KVDIM + kvh * DH;

    auto issue_tile = [&](int s, int k0) {
#pragma unroll
        for (int it = 0; it < 4; it++) {
            int chunk = it * 256 + tid;
            int row = chunk >> 4;
            int c8  = (chunk & 15) * 8;
            long go = (long)(k0 + row) * KVDIM + c8;
            uint32_t sb = smb + (uint32_t)(s * BUFH * 2 + (row * KSTR + c8) * 2);
            cpasync16(sb,               Kh + go);
            cpasync16(sb + PLN * 2,     Kl + go);
            cpasync16(sb + 2 * PLN * 2, Vh + go);
            cpasync16(sb + 3 * PLN * 2, Vl + go);
        }
    };

    float oc[16][4];
#pragma unroll
    for (int nt = 0; nt < 16; nt++)
#pragma unroll
        for (int r = 0; r < 4; r++) oc[nt][r] = 0.f;

    const int KT = 2 * qt + 2;
    issue_tile(0, 0);
    asm volatile("cp.async.commit_group;");

    for (int kt = 0; kt < KT; kt++) {
        const int s = kt & 1;
        if (kt + 1 < KT) {
            issue_tile(s ^ 1, (kt + 1) * 64);
            asm volatile("cp.async.commit_group;");
            asm volatile("cp.async.wait_group 1;");
        } else {
            asm volatile("cp.async.wait_group 0;");
        }
        __syncthreads();

        const uint32_t sbase = (uint32_t)(s * BUFH * 2);
        const int k0 = kt * 64;

        float sc[8][4];
#pragma unroll
        for (int nt = 0; nt < 8; nt++)
#pragma unroll
            for (int r = 0; r < 4; r++) sc[nt][r] = 0.f;

#pragma unroll
        for (int kk = 0; kk < 8; kk++) {
            uint32_t kh[4][4], kl[4][4];
#pragma unroll
            for (int j = 0; j < 4; j++) {
                ldsm_x4(kh[j], smb + sbase + koff_rel[j] + kk * 32);
                ldsm_x4(kl[j], smb + sbase + PLN * 2 + koff_rel[j] + kk * 32);
            }
#pragma unroll
            for (int j = 0; j < 4; j++)
#pragma unroll
                for (int hh = 0; hh < 2; hh++) {
                    const int nt = 2 * j + hh;
                    mma_f16(sc[nt], qhi[kk], &kh[j][2 * hh]);
                    mma_f16(sc[nt], qlo[kk], &kh[j][2 * hh]);
                    mma_f16(sc[nt], qhi[kk], &kl[j][2 * hh]);
                }
        }

        if (kt >= 2 * qt) {
            const int qr0 = q0 + r0, qr1 = q0 + r0 + 8;
#pragma unroll
            for (int nt = 0; nt < 8; nt++) {
                int c = k0 + nt * 8 + 2 * t;
                if (c     > qr0) sc[nt][0] = -1e30f;
                if (c + 1 > qr0) sc[nt][1] = -1e30f;
                if (c     > qr1) sc[nt][2] = -1e30f;
                if (c + 1 > qr1) sc[nt][3] = -1e30f;
            }
        }

        float mx0 = -1e30f, mx1 = -1e30f;
#pragma unroll
        for (int nt = 0; nt < 8; nt++) {
            mx0 = fmaxf(mx0, fmaxf(sc[nt][0], sc[nt][1]));
            mx1 = fmaxf(mx1, fmaxf(sc[nt][2], sc[nt][3]));
        }
        mx0 = fmaxf(mx0, __shfl_xor_sync(0xffffffffu, mx0, 1));
        mx0 = fmaxf(mx0, __shfl_xor_sync(0xffffffffu, mx0, 2));
        mx1 = fmaxf(mx1, __shfl_xor_sync(0xffffffffu, mx1, 1));
        mx1 = fmaxf(mx1, __shfl_xor_sync(0xffffffffu, mx1, 2));
        float mnew0 = fmaxf(m0, mx0);
        float mnew1 = fmaxf(m1, mx1);
        float corr0 = __expf(m0 - mnew0);
        float corr1 = __expf(m1 - mnew1);
        m0 = mnew0; m1 = mnew1;

        float sum0 = 0.f, sum1 = 0.f;
#pragma unroll
        for (int nt = 0; nt < 8; nt++) {
            float p00 = __expf(sc[nt][0] - mnew0);
            float p01 = __expf(sc[nt][1] - mnew0);
            float p10 = __expf(sc[nt][2] - mnew1);
            float p11 = __expf(sc[nt][3] - mnew1);
            sum0 += p00 + p01;
            sum1 += p10 + p11;
            int c = nt * 8 + 2 * t;
            uint32_t H, L;
            split2(p00, p01, H, L);
            *(uint32_t*)&Phi[r0 * PSTR + c] = H;
            *(uint32_t*)&Plo[r0 * PSTR + c] = L;
            split2(p10, p11, H, L);
            *(uint32_t*)&Phi[(r0 + 8) * PSTR + c] = H;
            *(uint32_t*)&Plo[(r0 + 8) * PSTR + c] = L;
        }
        sum0 += __shfl_xor_sync(0xffffffffu, sum0, 1);
        sum0 += __shfl_xor_sync(0xffffffffu, sum0, 2);
        sum1 += __shfl_xor_sync(0xffffffffu, sum1, 1);
        sum1 += __shfl_xor_sync(0xffffffffu, sum1, 2);
        l0 = l0 * corr0 + sum0;
        l1 = l1 * corr1 + sum1;

#pragma unroll
        for (int nt = 0; nt < 16; nt++) {
            oc[nt][0] *= corr0; oc[nt][1] *= corr0;
            oc[nt][2] *= corr1; oc[nt][3] *= corr1;
        }
        __syncwarp();

#pragma unroll
        for (int kk = 0; kk < 4; kk++) {
            uint32_t ph[4], pl[4];
            ldsm_x4(ph, smb + phoff + kk * 32);
            ldsm_x4(pl, smb + ploff + kk * 32);
#pragma unroll
            for (int vj = 0; vj < 8; vj++) {
                uint32_t vh4[4], vl4[4];
                ldsm_x4_t(vh4, smb + sbase + 2 * PLN * 2 + voff_rel[vj] + kk * 16 * VSTR * 2);
                ldsm_x4_t(vl4, smb + sbase + 3 * PLN * 2 + voff_rel[vj] + kk * 16 * VSTR * 2);
#pragma unroll
                for (int hh = 0; hh < 2; hh++) {
                    const int nt = 2 * vj + hh;
                    mma_f16(oc[nt], ph, &vh4[2 * hh]);
                    mma_f16(oc[nt], pl, &vh4[2 * hh]);
                    mma_f16(oc[nt], ph, &vl4[2 * hh]);
                }
            }
        }
        __syncthreads();
    }

    float linv0 = 1.f / l0;
    float linv1 = 1.f / l1;
    __half* Og = g_Oh + ((long)(b * TSEQ + q0)) * DIMC + h * DH;
#pragma unroll
    for (int nt = 0; nt < 16; nt++) {
        int c = nt * 8 + 2 * t;
        *(__half2*)&Og[(long)r0 * DIMC + c] =
            __floats2half2_rn(oc[nt][0] * linv0, oc[nt][1] * linv0);
        *(__half2*)&Og[(long)(r0 + 8) * DIMC + c] =
            __floats2half2_rn(oc[nt][2] * linv1, oc[nt][3] * linv1);
    }
}

// =====================================================================
// launch
// =====================================================================
extern "C" void kernel_launch(void* const* d_in, const int* in_sizes, int n_in,
                              void* d_out, int out_size) {
    const float* X  = (const float*)d_in[0];
    const float* Wq = (const float*)d_in[1];
    const float* Wk = (const float*)d_in[2];
    const float* Wv = (const float*)d_in[3];
    const float* Wo = (const float*)d_in[4];
    float* out = (float*)d_out;

    float  *QKVp;
    __half *Xh, *Wh, *Woh, *Oh;
    cudaGetSymbolAddress((void**)&QKVp, g_QKV);
    cudaGetSymbolAddress((void**)&Xh,  g_Xh);
    cudaGetSymbolAddress((void**)&Wh,  g_Wh);
    cudaGetSymbolAddress((void**)&Woh, g_Woh);
    cudaGetSymbolAddress((void**)&Oh,  g_Oh);

    cudaFuncSetAttribute(gemm_f16, cudaFuncAttributeMaxDynamicSharedMemorySize,
                         GEMM_SMEM_BYTES);
    cudaFuncSetAttribute(flash_tc, cudaFuncAttributeMaxDynamicSharedMemorySize,
                         FLASH_BYTES);

    rope_table<<<(TSEQ * 64 + 255) / 256, 256>>>();

    {
        int n4x = (BT * DIMC) / 4;
        pack_w<<<(n4x + 255) / 256, 256>>>(X, Xh, DIMC, 0, DIMC, n4x);
        int n4q = (DIMC * DIMC) / 4;
        pack_w<<<(n4q + 255) / 256, 256>>>(Wq, Wh, DIMC, 0, QKVN, n4q);
        int n4k = (DIMC * 1024) / 4;
        pack_w<<<(n4k + 255) / 256, 256>>>(Wk, Wh, 1024, KOFF, QKVN, n4k);
        pack_w<<<(n4k + 255) / 256, 256>>>(Wv, Wh, 1024, VOFF, QKVN, n4k);
        pack_w<<<(n4q + 255) / 256, 256>>>(Wo, Woh, DIMC, 0, DIMC, n4q);
    }

    gemm_f16<<<dim3(QKVN / 256, BT / 128), 256, GEMM_SMEM_BYTES>>>(Xh, Wh, QKVp, BT, QKVN, DIMC);

    {
        int totq = BT * NH * 64;
        rope_apply2<<<(totq + 255) / 256, 256>>>(QKVp, NH, QKVN, 0, totq);
        int totk = BT * NKV * 64;
        rope_apply2<<<(totk + 255) / 256, 256>>>(QKVp, NKV, QKVN, KOFF, totk);
    }

    {
        int n4 = (BT * KVDIM) / 4;
        split_kv<<<(n4 + 255) / 256, 256>>>(n4);
    }

    flash_tc<<<dim3(TSEQ / 128, BB * NH), 256, FLASH_BYTES>>>();

    gemm_f16<<<dim3(DIMC / 256, BT / 128), 256, GEMM_SMEM_BYTES>>>(Oh, Woh, out, BT, DIMC, DIMC);
}

// round 14
// speedup vs baseline: 1.1043x; 1.1043x over previous
#include <cuda_runtime.h>
#include <cuda_fp16.h>
#include <math.h>
#include <stdint.h>

#define DIMC   4096
#define NH     32
#define NKV    8
#define DH     128
#define BB     2
#define TSEQ   2048
#define BT     (BB * TSEQ)
#define QKVN   6144
#define KOFF   4096
#define VOFF   5120
#define KVDIM  1024

__device__ float  g_QKV[BT * QKVN];
__device__ __half g_Xh [BT * DIMC];
__device__ __half g_Wh [DIMC * QKVN];
__device__ __half g_Woh[DIMC * DIMC];
__device__ __half g_Oh [BT * DIMC];
__device__ __half g_Khi[BT * KVDIM];
__device__ __half g_Klo[BT * KVDIM];
__device__ __half g_Vhi[BT * KVDIM];
__device__ __half g_Vlo[BT * KVDIM];
__device__ float  g_cos[TSEQ * 64];
__device__ float  g_sin[TSEQ * 64];

// ---------------- helpers ----------------
__device__ __forceinline__ void mma_f16(float* c, const uint32_t* a, const uint32_t* b) {
    asm volatile(
        "mma.sync.aligned.m16n8k16.row.col.f32.f16.f16.f32 "
        "{%0,%1,%2,%3}, {%4,%5,%6,%7}, {%8,%9}, {%0,%1,%2,%3};"
        : "+f"(c[0]), "+f"(c[1]), "+f"(c[2]), "+f"(c[3])
        : "r"(a[0]), "r"(a[1]), "r"(a[2]), "r"(a[3]), "r"(b[0]), "r"(b[1]));
}
__device__ __forceinline__ void cpasync16(uint32_t dst, const void* src) {
    asm volatile("cp.async.cg.shared.global [%0], [%1], 16;" :: "r"(dst), "l"(src));
}
__device__ __forceinline__ void ldsm_x4(uint32_t* r, uint32_t addr) {
    asm volatile("ldmatrix.sync.aligned.m8n8.x4.shared.b16 {%0,%1,%2,%3}, [%4];"
                 : "=r"(r[0]), "=r"(r[1]), "=r"(r[2]), "=r"(r[3]) : "r"(addr));
}
__device__ __forceinline__ void ldsm_x4_t(uint32_t* r, uint32_t addr) {
    asm volatile("ldmatrix.sync.aligned.m8n8.x4.trans.shared.b16 {%0,%1,%2,%3}, [%4];"
                 : "=r"(r[0]), "=r"(r[1]), "=r"(r[2]), "=r"(r[3]) : "r"(addr));
}
__device__ __forceinline__ void split2(float a, float b, uint32_t& hi, uint32_t& lo) {
    __half ha = __float2half_rn(a), hb = __float2half_rn(b);
    __half la = __float2half_rn(a - __half2float(ha));
    __half lb = __float2half_rn(b - __half2float(hb));
    __half2 H = __halves2half2(ha, hb), L = __halves2half2(la, lb);
    hi = *(uint32_t*)&H; lo = *(uint32_t*)&L;
}

__global__ void pack_w(const float* __restrict__ src, __half* __restrict__ dst,
                       int w, int coff, int dstr, int n4) {
    int i = blockIdx.x * 256 + threadIdx.x;
    if (i >= n4) return;
    int idx = i * 4;
    int r = idx / w, c = idx % w;
    float4 v = *(const float4*)(src + idx);
    __half2* p = (__half2*)(dst + (long)r * dstr + coff + c);
    p[0] = __floats2half2_rn(v.x, v.y);
    p[1] = __floats2half2_rn(v.z, v.w);
}

// split K/V into fp16 hi/lo planes; K rope applied inline (reads RAW g_QKV).
// thread index: (bt, head, d4) with dlow = d4*4 < 64.
__global__ void split_kv(int total) {
    int i = blockIdx.x * 256 + threadIdx.x;
    if (i >= total) return;
    int d4 = i & 15;
    int hd = (i >> 4) & 7;
    int bt = i >> 7;
    int tok = bt & (TSEQ - 1);
    int dlo = d4 * 4;
    const float* base = g_QKV + (long)bt * QKVN;
    long o = (long)bt * KVDIM + hd * 128;

    float4 kL = *(const float4*)(base + KOFF + hd * 128 + dlo);
    float4 kH = *(const float4*)(base + KOFF + hd * 128 + dlo + 64);
    float4 cs = *(const float4*)(g_cos + tok * 64 + dlo);
    float4 sn = *(const float4*)(g_sin + tok * 64 + dlo);
    float4 oL, oH;
    oL.x = kL.x * cs.x - kH.x * sn.x;  oH.x = kL.x * sn.x + kH.x * cs.x;
    oL.y = kL.y * cs.y - kH.y * sn.y;  oH.y = kL.y * sn.y + kH.y * cs.y;
    oL.z = kL.z * cs.z - kH.z * sn.z;  oH.z = kL.z * sn.z + kH.z * cs.z;
    oL.w = kL.w * cs.w - kH.w * sn.w;  oH.w = kL.w * sn.w + kH.w * cs.w;

    uint32_t h01, l01, h23, l23;
    split2(oL.x, oL.y, h01, l01); split2(oL.z, oL.w, h23, l23);
    *(uint2*)&g_Khi[o + dlo] = make_uint2(h01, h23);
    *(uint2*)&g_Klo[o + dlo] = make_uint2(l01, l23);
    split2(oH.x, oH.y, h01, l01); split2(oH.z, oH.w, h23, l23);
    *(uint2*)&g_Khi[o + dlo + 64] = make_uint2(h01, h23);
    *(uint2*)&g_Klo[o + dlo + 64] = make_uint2(l01, l23);

    float4 vL = *(const float4*)(base + VOFF + hd * 128 + dlo);
    float4 vH = *(const float4*)(base + VOFF + hd * 128 + dlo + 64);
    split2(vL.x, vL.y, h01, l01); split2(vL.z, vL.w, h23, l23);
    *(uint2*)&g_Vhi[o + dlo] = make_uint2(h01, h23);
    *(uint2*)&g_Vlo[o + dlo] = make_uint2(l01, l23);
    split2(vH.x, vH.y, h01, l01); split2(vH.z, vH.w, h23, l23);
    *(uint2*)&g_Vhi[o + dlo + 64] = make_uint2(h01, h23);
    *(uint2*)&g_Vlo[o + dlo + 64] = make_uint2(l01, l23);
}

// =====================================================================
// FP16 GEMM (R12-exact: 128x128 CTA, warp 64x32, 2 CTAs/SM)
// =====================================================================
#define GBK  32
#define ASTR 40
#define BSTR 136
#define GEMM_SMEM_BYTES ((2 * 128 * ASTR + 2 * GBK * BSTR) * 2)

__global__ __launch_bounds__(256) void gemm_f16(const __half* __restrict__ A,
                                                const __half* __restrict__ B,
                                                float* __restrict__ C,
                                                int M, int N, int K) {
    extern __shared__ __half hsm[];
    __half* As = hsm;
    __half* Bs = hsm + 2 * 128 * ASTR;

    const int tid  = threadIdx.x;
    const int brow = blockIdx.y * 128;
    const int bcol = blockIdx.x * 128;
    const int wid  = tid >> 5, lane = tid & 31;
    const int g    = lane >> 2, t = lane & 3;
    const int m_base = (wid & 1) * 64;
    const int n_base = (wid >> 1) * 32;

    const int a_r = tid >> 2;
    const int a_c = (tid & 3) * 8;
    const int b_r = tid >> 4;
    const int b_c = (tid & 15) * 8;

    const int xr8 = lane & 15;
    const int xc8 = (lane >> 4) * 8;
    const uint32_t sAb = (uint32_t)__cvta_generic_to_shared(As);
    const uint32_t sBb = (uint32_t)__cvta_generic_to_shared(Bs);
    uint32_t aoff[4];
#pragma unroll
    for (int mi = 0; mi < 4; mi++)
        aoff[mi] = ((m_base + 16 * mi + xr8) * ASTR + xc8) * 2;
    uint32_t boff[2];
#pragma unroll
    for (int nj = 0; nj < 2; nj++)
        boff[nj] = (((lane & 7) + ((lane >> 3) & 1) * 8) * BSTR + n_base + nj * 16 + xc8) * 2;

    float c[4][4][4];
#pragma unroll
    for (int mi = 0; mi < 4; mi++)
#pragma unroll
        for (int ni = 0; ni < 4; ni++)
#pragma unroll
            for (int r = 0; r < 4; r++) c[mi][ni][r] = 0.f;

    const int KT = K / GBK;
    {
#pragma unroll
        for (int i = 0; i < 2; i++) {
            int r = a_r + 64 * i;
            cpasync16((uint32_t)__cvta_generic_to_shared(&As[r * ASTR + a_c]),
                      A + (long)(brow + r) * K + a_c);
        }
#pragma unroll
        for (int i = 0; i < 2; i++) {
            int r = b_r + 16 * i;
            cpasync16((uint32_t)__cvta_generic_to_shared(&Bs[r * BSTR + b_c]),
                      B + (long)r * N + bcol + b_c);
        }
        asm volatile("cp.async.commit_group;");
    }

    int s = 0;
    for (int kt = 0; kt < KT; kt++) {
        if (kt + 1 < KT) {
            const int k0 = (kt + 1) * GBK;
            __half* as = As + (s ^ 1) * 128 * ASTR;
            __half* bs = Bs + (s ^ 1) * GBK * BSTR;
#pragma unroll
            for (int i = 0; i < 2; i++) {
                int r = a_r + 64 * i;
                cpasync16((uint32_t)__cvta_generic_to_shared(&as[r * ASTR + a_c]),
                          A + (long)(brow + r) * K + k0 + a_c);
            }
#pragma unroll
            for (int i = 0; i < 2; i++) {
                int r = b_r + 16 * i;
                cpasync16((uint32_t)__cvta_generic_to_shared(&bs[r * BSTR + b_c]),
                          B + (long)(k0 + r) * N + bcol + b_c);
            }
            asm volatile("cp.async.commit_group;");
            asm volatile("cp.async.wait_group 1;");
        } else {
            asm volatile("cp.async.wait_group 0;");
        }
        __syncthreads();

        const uint32_t ab = sAb + (uint32_t)(s * 128 * ASTR * 2);
        const uint32_t bb = sBb + (uint32_t)(s * GBK * BSTR * 2);
#pragma unroll
        for (int j = 0; j < 2; j++) {
            uint32_t af[4][4], bq[2][4];
#pragma unroll
            for (int mi = 0; mi < 4; mi++)
                ldsm_x4(af[mi], ab + aoff[mi] + j * 32);
#pragma unroll
            for (int nj = 0; nj < 2; nj++)
                ldsm_x4_t(bq[nj], bb + boff[nj] + j * 16 * BSTR * 2);
#pragma unroll
            for (int mi = 0; mi < 4; mi++)
#pragma unroll
                for (int nj = 0; nj < 2; nj++) {
                    mma_f16(c[mi][2 * nj + 0], af[mi], &bq[nj][0]);
                    mma_f16(c[mi][2 * nj + 1], af[mi], &bq[nj][2]);
                }
        }
        __syncthreads();
        s ^= 1;
    }

#pragma unroll
    for (int mi = 0; mi < 4; mi++) {
#pragma unroll
        for (int ni = 0; ni < 4; ni++) {
            long row = brow + m_base + 16 * mi + g;
            int  col = bcol + n_base + 8 * ni + 2 * t;
            *(float2*)&C[row * N + col]       = make_float2(c[mi][ni][0], c[mi][ni][1]);
            *(float2*)&C[(row + 8) * N + col] = make_float2(c[mi][ni][2], c[mi][ni][3]);
        }
    }
}

// =====================================================================
// RoPE table
// =====================================================================
__global__ void rope_table() {
    int idx = blockIdx.x * 256 + threadIdx.x;
    if (idx >= TSEQ * 64) return;
    int d = idx & 63, t = idx >> 6;
    double inv = pow(10000.0, -(double)d / 64.0);
    double ang = (double)t * inv;
    g_cos[idx] = (float)cos(ang);
    g_sin[idx] = (float)sin(ang);
}

// =====================================================================
// Flash attention v4: 128-row Q tiles, warp-private softmax, fp16 3-term
// mma, pre-split K/V planes, cp.async pipeline, Q-rope fused in registers,
// longest-first CTA order.
// =====================================================================
#define KSTR 136
#define VSTR 136
#define PSTR 72
#define PLN   (64 * KSTR)
#define BUFH  (4 * PLN)
#define PHI_H (2 * BUFH)
#define PLO_H (PHI_H + 128 * PSTR)
#define FLASH_BYTES ((PLO_H + 128 * PSTR) * 2)

__global__ __launch_bounds__(256, 1) void flash_tc() {
    extern __shared__ __half hs[];
    __half* Phi = hs + PHI_H;
    __half* Plo = hs + PLO_H;

    const int tid = threadIdx.x;
    const int qt  = (int)(gridDim.x - 1 - blockIdx.x);   // longest work first
    const int bh  = blockIdx.y;
    const int b   = bh >> 5;
    const int h   = bh & 31;
    const int kvh = h >> 2;
    const int q0  = qt * 128;
    const int lane = tid & 31, wid = tid >> 5;
    const int g = lane >> 2, t = lane & 3;
    const int wm = wid;
    const int r0 = wm * 16 + g;

    const uint32_t smb = (uint32_t)__cvta_generic_to_shared(hs);
    const int n_loc  = (lane & 7) + ((lane >> 4) << 3);
    const int k_half = (lane >> 3) & 1;
    uint32_t koff_rel[4];
#pragma unroll
    for (int j = 0; j < 4; j++)
        koff_rel[j] = ((j * 16 + n_loc) * KSTR + k_half * 8) * 2;
    const int xr  = lane & 15;
    const int xc8 = (lane >> 4) * 8;
    const uint32_t phoff = (PHI_H + (wm * 16 + xr) * PSTR + xc8) * 2;
    const uint32_t ploff = (PLO_H + (wm * 16 + xr) * PSTR + xc8) * 2;
    const int xrv = (lane & 7) + ((lane >> 3) & 1) * 8;
    uint32_t voff_rel[8];
#pragma unroll
    for (int vj = 0; vj < 8; vj++)
        voff_rel[vj] = (xrv * VSTR + vj * 16 + xc8) * 2;

    // ---- Q fragments: load raw, rope in registers, scale, split ----
    const float scale = 0.0883883476483184f;
    uint32_t qhi[8][4], qlo[8][4];
    {
        const float* Qg = g_QKV + ((long)(b * TSEQ + q0)) * QKVN + h * DH;
        float2 raw[8][4];
#pragma unroll
        for (int kk = 0; kk < 8; kk++) {
            const int c = kk * 16 + 2 * t;
            raw[kk][0] = *(const float2*)&Qg[(long)r0 * QKVN + c];
            raw[kk][1] = *(const float2*)&Qg[(long)(r0 + 8) * QKVN + c];
            raw[kk][2] = *(const float2*)&Qg[(long)r0 * QKVN + c + 8];
            raw[kk][3] = *(const float2*)&Qg[(long)(r0 + 8) * QKVN + c + 8];
        }
        const int tok0 = q0 + r0, tok1 = tok0 + 8;
#pragma unroll
        for (int kk = 0; kk < 4; kk++) {
            const int dbase = kk * 16 + 2 * t;   // < 64
#pragma unroll
            for (int si = 0; si < 4; si++) {
                const int tok  = (si & 1) ? tok1 : tok0;
                const int doff = (si & 2) ? 8 : 0;
                float2 cc = *(const float2*)&g_cos[tok * 64 + dbase + doff];
                float2 ss = *(const float2*)&g_sin[tok * 64 + dbase + doff];
                float2 lo2 = raw[kk][si], hi2 = raw[kk + 4][si];
                float olx = lo2.x * cc.x - hi2.x * ss.x;
                float ohx = lo2.x * ss.x + hi2.x * cc.x;
                float oly = lo2.y * cc.y - hi2.y * ss.y;
                float ohy = lo2.y * ss.y + hi2.y * cc.y;
                split2(olx * scale, oly * scale, qhi[kk][si],     qlo[kk][si]);
                split2(ohx * scale, ohy * scale, qhi[kk + 4][si], qlo[kk + 4][si]);
            }
        }
    }
    float m0 = -1e30f, m1 = -1e30f, l0 = 0.f, l1 = 0.f;

    const __half* Kh = g_Khi + (long)(b * TSEQ) * KVDIM + kvh * DH;
    const __half* Kl = g_Klo + (long)(b * TSEQ) * KVDIM + kvh * DH;
    const __half* Vh = g_Vhi + (long)(b * TSEQ) * KVDIM + kvh * DH;
    const __half* Vl = g_Vlo + (long)(b * TSEQ) * KVDIM + kvh * DH;

    auto issue_tile = [&](int s, int k0) {
#pragma unroll
        for (int it = 0; it < 4; it++) {
            int chunk = it * 256 + tid;
            int row = chunk >> 4;
            int c8  = (chunk & 15) * 8;
            long go = (long)(k0 + row) * KVDIM + c8;
            uint32_t sb = smb + (uint32_t)(s * BUFH * 2 + (row * KSTR + c8) * 2);
            cpasync16(sb,               Kh + go);
            cpasync16(sb + PLN * 2,     Kl + go);
            cpasync16(sb + 2 * PLN * 2, Vh + go);
            cpasync16(sb + 3 * PLN * 2, Vl + go);
        }
    };

    float oc[16][4];
#pragma unroll
    for (int nt = 0; nt < 16; nt++)
#pragma unroll
        for (int r = 0; r < 4; r++) oc[nt][r] = 0.f;

    const int KT = 2 * qt + 2;
    issue_tile(0, 0);
    asm volatile("cp.async.commit_group;");

    for (int kt = 0; kt < KT; kt++) {
        const int s = kt & 1;
        if (kt + 1 < KT) {
            issue_tile(s ^ 1, (kt + 1) * 64);
            asm volatile("cp.async.commit_group;");
            asm volatile("cp.async.wait_group 1;");
        } else {
            asm volatile("cp.async.wait_group 0;");
        }
        __syncthreads();

        const uint32_t sbase = (uint32_t)(s * BUFH * 2);
        const int k0 = kt * 64;

        float sc[8][4];
#pragma unroll
        for (int nt = 0; nt < 8; nt++)
#pragma unroll
            for (int r = 0; r < 4; r++) sc[nt][r] = 0.f;

#pragma unroll
        for (int kk = 0; kk < 8; kk++) {
            uint32_t kh[4][4], kl[4][4];
#pragma unroll
            for (int j = 0; j < 4; j++) {
                ldsm_x4(kh[j], smb + sbase + koff_rel[j] + kk * 32);
                ldsm_x4(kl[j], smb + sbase + PLN * 2 + koff_rel[j] + kk * 32);
            }
#pragma unroll
            for (int j = 0; j < 4; j++)
#pragma unroll
                for (int hh = 0; hh < 2; hh++) {
                    const int nt = 2 * j + hh;
                    mma_f16(sc[nt], qhi[kk], &kh[j][2 * hh]);
                    mma_f16(sc[nt], qlo[kk], &kh[j][2 * hh]);
                    mma_f16(sc[nt], qhi[kk], &kl[j][2 * hh]);
                }
        }

        if (kt >= 2 * qt) {
            const int qr0 = q0 + r0, qr1 = q0 + r0 + 8;
#pragma unroll
            for (int nt = 0; nt < 8; nt++) {
                int c = k0 + nt * 8 + 2 * t;
                if (c     > qr0) sc[nt][0] = -1e30f;
                if (c + 1 > qr0) sc[nt][1] = -1e30f;
                if (c     > qr1) sc[nt][2] = -1e30f;
                if (c + 1 > qr1) sc[nt][3] = -1e30f;
            }
        }

        float mx0 = -1e30f, mx1 = -1e30f;
#pragma unroll
        for (int nt = 0; nt < 8; nt++) {
            mx0 = fmaxf(mx0, fmaxf(sc[nt][0], sc[nt][1]));
            mx1 = fmaxf(mx1, fmaxf(sc[nt][2], sc[nt][3]));
        }
        mx0 = fmaxf(mx0, __shfl_xor_sync(0xffffffffu, mx0, 1));
        mx0 = fmaxf(mx0, __shfl_xor_sync(0xffffffffu, mx0, 2));
        mx1 = fmaxf(mx1, __shfl_xor_sync(0xffffffffu, mx1, 1));
        mx1 = fmaxf(mx1, __shfl_xor_sync(0xffffffffu, mx1, 2));
        float mnew0 = fmaxf(m0, mx0);
        float mnew1 = fmaxf(m1, mx1);
        float corr0 = __expf(m0 - mnew0);
        float corr1 = __expf(m1 - mnew1);
        m0 = mnew0; m1 = mnew1;

        float sum0 = 0.f, sum1 = 0.f;
#pragma unroll
        for (int nt = 0; nt < 8; nt++) {
            float p00 = __expf(sc[nt][0] - mnew0);
            float p01 = __expf(sc[nt][1] - mnew0);
            float p10 = __expf(sc[nt][2] - mnew1);
            float p11 = __expf(sc[nt][3] - mnew1);
            sum0 += p00 + p01;
            sum1 += p10 + p11;
            int c = nt * 8 + 2 * t;
            uint32_t H, L;
            split2(p00, p01, H, L);
            *(uint32_t*)&Phi[r0 * PSTR + c] = H;
            *(uint32_t*)&Plo[r0 * PSTR + c] = L;
            split2(p10, p11, H, L);
            *(uint32_t*)&Phi[(r0 + 8) * PSTR + c] = H;
            *(uint32_t*)&Plo[(r0 + 8) * PSTR + c] = L;
        }
        sum0 += __shfl_xor_sync(0xffffffffu, sum0, 1);
        sum0 += __shfl_xor_sync(0xffffffffu, sum0, 2);
        sum1 += __shfl_xor_sync(0xffffffffu, sum1, 1);
        sum1 += __shfl_xor_sync(0xffffffffu, sum1, 2);
        l0 = l0 * corr0 + sum0;
        l1 = l1 * corr1 + sum1;

#pragma unroll
        for (int nt = 0; nt < 16; nt++) {
            oc[nt][0] *= corr0; oc[nt][1] *= corr0;
            oc[nt][2] *= corr1; oc[nt][3] *= corr1;
        }
        __syncwarp();

#pragma unroll
        for (int kk = 0; kk < 4; kk++) {
            uint32_t ph[4], pl[4];
            ldsm_x4(ph, smb + phoff + kk * 32);
            ldsm_x4(pl, smb + ploff + kk * 32);
#pragma unroll
            for (int vj = 0; vj < 8; vj++) {
                uint32_t vh4[4], vl4[4];
                ldsm_x4_t(vh4, smb + sbase + 2 * PLN * 2 + voff_rel[vj] + kk * 16 * VSTR * 2);
                ldsm_x4_t(vl4, smb + sbase + 3 * PLN * 2 + voff_rel[vj] + kk * 16 * VSTR * 2);
#pragma unroll
                for (int hh = 0; hh < 2; hh++) {
                    const int nt = 2 * vj + hh;
                    mma_f16(oc[nt], ph, &vh4[2 * hh]);
                    mma_f16(oc[nt], pl, &vh4[2 * hh]);
                    mma_f16(oc[nt], ph, &vl4[2 * hh]);
                }
            }
        }
        __syncthreads();
    }

    float linv0 = 1.f / l0;
    float linv1 = 1.f / l1;
    __half* Og = g_Oh + ((long)(b * TSEQ + q0)) * DIMC + h * DH;
#pragma unroll
    for (int nt = 0; nt < 16; nt++) {
        int c = nt * 8 + 2 * t;
        *(__half2*)&Og[(long)r0 * DIMC + c] =
            __floats2half2_rn(oc[nt][0] * linv0, oc[nt][1] * linv0);
        *(__half2*)&Og[(long)(r0 + 8) * DIMC + c] =
            __floats2half2_rn(oc[nt][2] * linv1, oc[nt][3] * linv1);
    }
}

// =====================================================================
// launch
// =====================================================================
extern "C" void kernel_launch(void* const* d_in, const int* in_sizes, int n_in,
                              void* d_out, int out_size) {
    const float* X  = (const float*)d_in[0];
    const float* Wq = (const float*)d_in[1];
    const float* Wk = (const float*)d_in[2];
    const float* Wv = (const float*)d_in[3];
    const float* Wo = (const float*)d_in[4];
    float* out = (float*)d_out;

    float  *QKVp;
    __half *Xh, *Wh, *Woh, *Oh;
    cudaGetSymbolAddress((void**)&QKVp, g_QKV);
    cudaGetSymbolAddress((void**)&Xh,  g_Xh);
    cudaGetSymbolAddress((void**)&Wh,  g_Wh);
    cudaGetSymbolAddress((void**)&Woh, g_Woh);
    cudaGetSymbolAddress((void**)&Oh,  g_Oh);

    cudaFuncSetAttribute(gemm_f16, cudaFuncAttributeMaxDynamicSharedMemorySize,
                         GEMM_SMEM_BYTES);
    cudaFuncSetAttribute(flash_tc, cudaFuncAttributeMaxDynamicSharedMemorySize,
                         FLASH_BYTES);

    rope_table<<<(TSEQ * 64 + 255) / 256, 256>>>();

    {
        int n4x = (BT * DIMC) / 4;
        pack_w<<<(n4x + 255) / 256, 256>>>(X, Xh, DIMC, 0, DIMC, n4x);
        int n4q = (DIMC * DIMC) / 4;
        pack_w<<<(n4q + 255) / 256, 256>>>(Wq, Wh, DIMC, 0, QKVN, n4q);
        int n4k = (DIMC * 1024) / 4;
        pack_w<<<(n4k + 255) / 256, 256>>>(Wk, Wh, 1024, KOFF, QKVN, n4k);
        pack_w<<<(n4k + 255) / 256, 256>>>(Wv, Wh, 1024, VOFF, QKVN, n4k);
        pack_w<<<(n4q + 255) / 256, 256>>>(Wo, Woh, DIMC, 0, DIMC, n4q);
    }

    gemm_f16<<<dim3(QKVN / 128, BT / 128), 256, GEMM_SMEM_BYTES>>>(Xh, Wh, QKVp, BT, QKVN, DIMC);

    // K rope + K/V hi/lo split (fused, one pass)
    {
        int total = BT * 8 * 16;
        split_kv<<<(total + 255) / 256, 256>>>(total);
    }

    flash_tc<<<dim3(TSEQ / 128, BB * NH), 256, FLASH_BYTES>>>();

    gemm_f16<<<dim3(DIMC / 128, BT / 128), 256, GEMM_SMEM_BYTES>>>(Oh, Woh, out, BT, DIMC, DIMC);
}

// round 15
// speedup vs baseline: 1.1730x; 1.0623x over previous
#include <cuda_runtime.h>
#include <cuda_fp16.h>
#include <math.h>
#include <stdint.h>

#define DIMC   4096
#define NH     32
#define NKV    8
#define DH     128
#define BB     2
#define TSEQ   2048
#define BT     (BB * TSEQ)
#define QKVN   6144
#define KOFF   4096
#define VOFF   5120
#define KVDIM  1024

__device__ float  g_QKV[BT * QKVN];
__device__ __half g_Xh [BT * DIMC];
__device__ __half g_Wh [DIMC * QKVN];
__device__ __half g_Woh[DIMC * DIMC];
__device__ __half g_Oh [BT * DIMC];
__device__ __half g_Khi[BT * KVDIM];
__device__ __half g_Klo[BT * KVDIM];
__device__ __half g_Vhi[BT * KVDIM];
__device__ __half g_Vlo[BT * KVDIM];
__device__ float  g_cos[TSEQ * 64];
__device__ float  g_sin[TSEQ * 64];

// ---------------- helpers ----------------
__device__ __forceinline__ void mma_f16(float* c, const uint32_t* a, const uint32_t* b) {
    asm volatile(
        "mma.sync.aligned.m16n8k16.row.col.f32.f16.f16.f32 "
        "{%0,%1,%2,%3}, {%4,%5,%6,%7}, {%8,%9}, {%0,%1,%2,%3};"
        : "+f"(c[0]), "+f"(c[1]), "+f"(c[2]), "+f"(c[3])
        : "r"(a[0]), "r"(a[1]), "r"(a[2]), "r"(a[3]), "r"(b[0]), "r"(b[1]));
}
__device__ __forceinline__ void cpasync16(uint32_t dst, const void* src) {
    asm volatile("cp.async.cg.shared.global [%0], [%1], 16;" :: "r"(dst), "l"(src));
}
__device__ __forceinline__ void ldsm_x4(uint32_t* r, uint32_t addr) {
    asm volatile("ldmatrix.sync.aligned.m8n8.x4.shared.b16 {%0,%1,%2,%3}, [%4];"
                 : "=r"(r[0]), "=r"(r[1]), "=r"(r[2]), "=r"(r[3]) : "r"(addr));
}
__device__ __forceinline__ void ldsm_x4_t(uint32_t* r, uint32_t addr) {
    asm volatile("ldmatrix.sync.aligned.m8n8.x4.trans.shared.b16 {%0,%1,%2,%3}, [%4];"
                 : "=r"(r[0]), "=r"(r[1]), "=r"(r[2]), "=r"(r[3]) : "r"(addr));
}
__device__ __forceinline__ void split2(float a, float b, uint32_t& hi, uint32_t& lo) {
    __half ha = __float2half_rn(a), hb = __float2half_rn(b);
    __half la = __float2half_rn(a - __half2float(ha));
    __half lb = __float2half_rn(b - __half2float(hb));
    __half2 H = __halves2half2(ha, hb), L = __halves2half2(la, lb);
    hi = *(uint32_t*)&H; lo = *(uint32_t*)&L;
}

__global__ void pack_w(const float* __restrict__ src, __half* __restrict__ dst,
                       int w, int coff, int dstr, int n4) {
    int i = blockIdx.x * 256 + threadIdx.x;
    if (i >= n4) return;
    int idx = i * 4;
    int r = idx / w, c = idx % w;
    float4 v = *(const float4*)(src + idx);
    __half2* p = (__half2*)(dst + (long)r * dstr + coff + c);
    p[0] = __floats2half2_rn(v.x, v.y);
    p[1] = __floats2half2_rn(v.z, v.w);
}

// split K/V into fp16 hi/lo planes; K rope applied inline.
__global__ void split_kv(int total) {
    int i = blockIdx.x * 256 + threadIdx.x;
    if (i >= total) return;
    int d4 = i & 15;
    int hd = (i >> 4) & 7;
    int bt = i >> 7;
    int tok = bt & (TSEQ - 1);
    int dlo = d4 * 4;
    const float* base = g_QKV + (long)bt * QKVN;
    long o = (long)bt * KVDIM + hd * 128;

    float4 kL = *(const float4*)(base + KOFF + hd * 128 + dlo);
    float4 kH = *(const float4*)(base + KOFF + hd * 128 + dlo + 64);
    float4 cs = *(const float4*)(g_cos + tok * 64 + dlo);
    float4 sn = *(const float4*)(g_sin + tok * 64 + dlo);
    float4 oL, oH;
    oL.x = kL.x * cs.x - kH.x * sn.x;  oH.x = kL.x * sn.x + kH.x * cs.x;
    oL.y = kL.y * cs.y - kH.y * sn.y;  oH.y = kL.y * sn.y + kH.y * cs.y;
    oL.z = kL.z * cs.z - kH.z * sn.z;  oH.z = kL.z * sn.z + kH.z * cs.z;
    oL.w = kL.w * cs.w - kH.w * sn.w;  oH.w = kL.w * sn.w + kH.w * cs.w;

    uint32_t h01, l01, h23, l23;
    split2(oL.x, oL.y, h01, l01); split2(oL.z, oL.w, h23, l23);
    *(uint2*)&g_Khi[o + dlo] = make_uint2(h01, h23);
    *(uint2*)&g_Klo[o + dlo] = make_uint2(l01, l23);
    split2(oH.x, oH.y, h01, l01); split2(oH.z, oH.w, h23, l23);
    *(uint2*)&g_Khi[o + dlo + 64] = make_uint2(h01, h23);
    *(uint2*)&g_Klo[o + dlo + 64] = make_uint2(l01, l23);

    float4 vL = *(const float4*)(base + VOFF + hd * 128 + dlo);
    float4 vH = *(const float4*)(base + VOFF + hd * 128 + dlo + 64);
    split2(vL.x, vL.y, h01, l01); split2(vL.z, vL.w, h23, l23);
    *(uint2*)&g_Vhi[o + dlo] = make_uint2(h01, h23);
    *(uint2*)&g_Vlo[o + dlo] = make_uint2(l01, l23);
    split2(vH.x, vH.y, h01, l01); split2(vH.z, vH.w, h23, l23);
    *(uint2*)&g_Vhi[o + dlo + 64] = make_uint2(h01, h23);
    *(uint2*)&g_Vlo[o + dlo + 64] = make_uint2(l01, l23);
}

// =====================================================================
// FP16 GEMM v3: CTA 128x128, warp tile 64x32, BK=64 (half the barriers),
// cp.async double buffer, 2 CTAs/SM. Same k order -> bit-identical C.
// =====================================================================
#define GBK   64
#define ASTR  72    // halves; 144 B row ≡ 16 mod 128 -> conflict-free ldsm
#define BSTR  136   // halves; 272 B row ≡ 16 mod 128
#define GEMM_SMEM_BYTES ((2 * 128 * ASTR + 2 * GBK * BSTR) * 2)   // 71680

__global__ __launch_bounds__(256) void gemm_f16(const __half* __restrict__ A,
                                                const __half* __restrict__ B,
                                                float* __restrict__ C,
                                                int M, int N, int K) {
    extern __shared__ __half hsm[];
    __half* As = hsm;                      // [2][128][ASTR]
    __half* Bs = hsm + 2 * 128 * ASTR;     // [2][GBK][BSTR]

    const int tid  = threadIdx.x;
    const int brow = blockIdx.y * 128;
    const int bcol = blockIdx.x * 128;
    const int wid  = tid >> 5, lane = tid & 31;
    const int g    = lane >> 2, t = lane & 3;
    const int m_base = (wid & 1) * 64;
    const int n_base = (wid >> 1) * 32;

    // loaders (16B = 8 halves); A: 128x64 = 1024 chunks; B: 64x128 = 1024 chunks
    const int a_r = tid >> 1;              // wrong granularity? use chunk decode below
    const int xr8 = lane & 15;
    const int xc8 = (lane >> 4) * 8;
    const uint32_t sAb = (uint32_t)__cvta_generic_to_shared(As);
    const uint32_t sBb = (uint32_t)__cvta_generic_to_shared(Bs);
    uint32_t aoff[4];
#pragma unroll
    for (int mi = 0; mi < 4; mi++)
        aoff[mi] = ((m_base + 16 * mi + xr8) * ASTR + xc8) * 2;
    uint32_t boff[2];
#pragma unroll
    for (int nj = 0; nj < 2; nj++)
        boff[nj] = (((lane & 7) + ((lane >> 3) & 1) * 8) * BSTR + n_base + nj * 16 + xc8) * 2;

    float c[4][4][4];
#pragma unroll
    for (int mi = 0; mi < 4; mi++)
#pragma unroll
        for (int ni = 0; ni < 4; ni++)
#pragma unroll
            for (int r = 0; r < 4; r++) c[mi][ni][r] = 0.f;

    auto load_tile = [&](__half* as, __half* bs, const __half* Ap, const __half* Bp, int k0) {
#pragma unroll
        for (int it = 0; it < 4; it++) {
            int chunk = it * 256 + tid;        // A: 1024 chunks of 8 halves
            int r = chunk >> 3, c8 = (chunk & 7) * 8;
            cpasync16((uint32_t)__cvta_generic_to_shared(&as[r * ASTR + c8]),
                      Ap + (long)(brow + r) * K + k0 + c8);
        }
#pragma unroll
        for (int it = 0; it < 4; it++) {
            int chunk = it * 256 + tid;        // B: 1024 chunks
            int r = chunk >> 4, c8 = (chunk & 15) * 8;
            cpasync16((uint32_t)__cvta_generic_to_shared(&bs[r * BSTR + c8]),
                      Bp + (long)(k0 + r) * N + bcol + c8);
        }
    };

    const int KT = K / GBK;
    load_tile(As, Bs, A, B, 0);
    asm volatile("cp.async.commit_group;");

    int s = 0;
    for (int kt = 0; kt < KT; kt++) {
        if (kt + 1 < KT) {
            load_tile(As + (s ^ 1) * 128 * ASTR, Bs + (s ^ 1) * GBK * BSTR,
                      A, B, (kt + 1) * GBK);
            asm volatile("cp.async.commit_group;");
            asm volatile("cp.async.wait_group 1;");
        } else {
            asm volatile("cp.async.wait_group 0;");
        }
        __syncthreads();

        const uint32_t ab = sAb + (uint32_t)(s * 128 * ASTR * 2);
        const uint32_t bb = sBb + (uint32_t)(s * GBK * BSTR * 2);
#pragma unroll
        for (int j = 0; j < 4; j++) {          // four k16 steps (ascending k)
            uint32_t af[4][4], bq[2][4];
#pragma unroll
            for (int mi = 0; mi < 4; mi++)
                ldsm_x4(af[mi], ab + aoff[mi] + j * 32);
#pragma unroll
            for (int nj = 0; nj < 2; nj++)
                ldsm_x4_t(bq[nj], bb + boff[nj] + j * 16 * BSTR * 2);
#pragma unroll
            for (int mi = 0; mi < 4; mi++)
#pragma unroll
                for (int nj = 0; nj < 2; nj++) {
                    mma_f16(c[mi][2 * nj + 0], af[mi], &bq[nj][0]);
                    mma_f16(c[mi][2 * nj + 1], af[mi], &bq[nj][2]);
                }
        }
        __syncthreads();
        s ^= 1;
    }

#pragma unroll
    for (int mi = 0; mi < 4; mi++) {
#pragma unroll
        for (int ni = 0; ni < 4; ni++) {
            long row = brow + m_base + 16 * mi + g;
            int  col = bcol + n_base + 8 * ni + 2 * t;
            *(float2*)&C[row * N + col]       = make_float2(c[mi][ni][0], c[mi][ni][1]);
            *(float2*)&C[(row + 8) * N + col] = make_float2(c[mi][ni][2], c[mi][ni][3]);
        }
    }
}

// =====================================================================
// RoPE table
// =====================================================================
__global__ void rope_table() {
    int idx = blockIdx.x * 256 + threadIdx.x;
    if (idx >= TSEQ * 64) return;
    int d = idx & 63, t = idx >> 6;
    double inv = pow(10000.0, -(double)d / 64.0);
    double ang = (double)t * inv;
    g_cos[idx] = (float)cos(ang);
    g_sin[idx] = (float)sin(ang);
}

// =====================================================================
// Flash attention v4 (R14-exact)
// =====================================================================
#define KSTR 136
#define VSTR 136
#define PSTR 72
#define PLN   (64 * KSTR)
#define BUFH  (4 * PLN)
#define PHI_H (2 * BUFH)
#define PLO_H (PHI_H + 128 * PSTR)
#define FLASH_BYTES ((PLO_H + 128 * PSTR) * 2)

__global__ __launch_bounds__(256, 1) void flash_tc() {
    extern __shared__ __half hs[];
    __half* Phi = hs + PHI_H;
    __half* Plo = hs + PLO_H;

    const int tid = threadIdx.x;
    const int qt  = (int)(gridDim.x - 1 - blockIdx.x);
    const int bh  = blockIdx.y;
    const int b   = bh >> 5;
    const int h   = bh & 31;
    const int kvh = h >> 2;
    const int q0  = qt * 128;
    const int lane = tid & 31, wid = tid >> 5;
    const int g = lane >> 2, t = lane & 3;
    const int wm = wid;
    const int r0 = wm * 16 + g;

    const uint32_t smb = (uint32_t)__cvta_generic_to_shared(hs);
    const int n_loc  = (lane & 7) + ((lane >> 4) << 3);
    const int k_half = (lane >> 3) & 1;
    uint32_t koff_rel[4];
#pragma unroll
    for (int j = 0; j < 4; j++)
        koff_rel[j] = ((j * 16 + n_loc) * KSTR + k_half * 8) * 2;
    const int xr  = lane & 15;
    const int xc8 = (lane >> 4) * 8;
    const uint32_t phoff = (PHI_H + (wm * 16 + xr) * PSTR + xc8) * 2;
    const uint32_t ploff = (PLO_H + (wm * 16 + xr) * PSTR + xc8) * 2;
    const int xrv = (lane & 7) + ((lane >> 3) & 1) * 8;
    uint32_t voff_rel[8];
#pragma unroll
    for (int vj = 0; vj < 8; vj++)
        voff_rel[vj] = (xrv * VSTR + vj * 16 + xc8) * 2;

    const float scale = 0.0883883476483184f;
    uint32_t qhi[8][4], qlo[8][4];
    {
        const float* Qg = g_QKV + ((long)(b * TSEQ + q0)) * QKVN + h * DH;
        float2 raw[8][4];
#pragma unroll
        for (int kk = 0; kk < 8; kk++) {
            const int c = kk * 16 + 2 * t;
            raw[kk][0] = *(const float2*)&Qg[(long)r0 * QKVN + c];
            raw[kk][1] = *(const float2*)&Qg[(long)(r0 + 8) * QKVN + c];
            raw[kk][2] = *(const float2*)&Qg[(long)r0 * QKVN + c + 8];
            raw[kk][3] = *(const float2*)&Qg[(long)(r0 + 8) * QKVN + c + 8];
        }
        const int tok0 = q0 + r0, tok1 = tok0 + 8;
#pragma unroll
        for (int kk = 0; kk < 4; kk++) {
            const int dbase = kk * 16 + 2 * t;
#pragma unroll
            for (int si = 0; si < 4; si++) {
                const int tok  = (si & 1) ? tok1 : tok0;
                const int doff = (si & 2) ? 8 : 0;
                float2 cc = *(const float2*)&g_cos[tok * 64 + dbase + doff];
                float2 ss = *(const float2*)&g_sin[tok * 64 + dbase + doff];
                float2 lo2 = raw[kk][si], hi2 = raw[kk + 4][si];
                float olx = lo2.x * cc.x - hi2.x * ss.x;
                float ohx = lo2.x * ss.x + hi2.x * cc.x;
                float oly = lo2.y * cc.y - hi2.y * ss.y;
                float ohy = lo2.y * ss.y + hi2.y * cc.y;
                split2(olx * scale, oly * scale, qhi[kk][si],     qlo[kk][si]);
                split2(ohx * scale, ohy * scale, qhi[kk + 4][si], qlo[kk + 4][si]);
            }
        }
    }
    float m0 = -1e30f, m1 = -1e30f, l0 = 0.f, l1 = 0.f;

    const __half* Kh = g_Khi + (long)(b * TSEQ) * KVDIM + kvh * DH;
    const __half* Kl = g_Klo + (long)(b * TSEQ) * KVDIM + kvh * DH;
    const __half* Vh = g_Vhi + (long)(b * TSEQ) * KVDIM + kvh * DH;
    const __half* Vl = g_Vlo + (long)(b * TSEQ) * KVDIM + kvh * DH;

    auto issue_tile = [&](int s, int k0) {
#pragma unroll
        for (int it = 0; it < 4; it++) {
            int chunk = it * 256 + tid;
            int row = chunk >> 4;
            int c8  = (chunk & 15) * 8;
            long go = (long)(k0 + row) * KVDIM + c8;
            uint32_t sb = smb + (uint32_t)(s * BUFH * 2 + (row * KSTR + c8) * 2);
            cpasync16(sb,               Kh + go);
            cpasync16(sb + PLN * 2,     Kl + go);
            cpasync16(sb + 2 * PLN * 2, Vh + go);
            cpasync16(sb + 3 * PLN * 2, Vl + go);
        }
    };

    float oc[16][4];
#pragma unroll
    for (int nt = 0; nt < 16; nt++)
#pragma unroll
        for (int r = 0; r < 4; r++) oc[nt][r] = 0.f;

    const int KT = 2 * qt + 2;
    issue_tile(0, 0);
    asm volatile("cp.async.commit_group;");

    for (int kt = 0; kt < KT; kt++) {
        const int s = kt & 1;
        if (kt + 1 < KT) {
            issue_tile(s ^ 1, (kt + 1) * 64);
            asm volatile("cp.async.commit_group;");
            asm volatile("cp.async.wait_group 1;");
        } else {
            asm volatile("cp.async.wait_group 0;");
        }
        __syncthreads();

        const uint32_t sbase = (uint32_t)(s * BUFH * 2);
        const int k0 = kt * 64;

        float sc[8][4];
#pragma unroll
        for (int nt = 0; nt < 8; nt++)
#pragma unroll
            for (int r = 0; r < 4; r++) sc[nt][r] = 0.f;

#pragma unroll
        for (int kk = 0; kk < 8; kk++) {
            uint32_t kh[4][4], kl[4][4];
#pragma unroll
            for (int j = 0; j < 4; j++) {
                ldsm_x4(kh[j], smb + sbase + koff_rel[j] + kk * 32);
                ldsm_x4(kl[j], smb + sbase + PLN * 2 + koff_rel[j] + kk * 32);
            }
#pragma unroll
            for (int j = 0; j < 4; j++)
#pragma unroll
                for (int hh = 0; hh < 2; hh++) {
                    const int nt = 2 * j + hh;
                    mma_f16(sc[nt], qhi[kk], &kh[j][2 * hh]);
                    mma_f16(sc[nt], qlo[kk], &kh[j][2 * hh]);
                    mma_f16(sc[nt], qhi[kk], &kl[j][2 * hh]);
                }
        }

        if (kt >= 2 * qt) {
            const int qr0 = q0 + r0, qr1 = q0 + r0 + 8;
#pragma unroll
            for (int nt = 0; nt < 8; nt++) {
                int c = k0 + nt * 8 + 2 * t;
                if (c     > qr0) sc[nt][0] = -1e30f;
                if (c + 1 > qr0) sc[nt][1] = -1e30f;
                if (c     > qr1) sc[nt][2] = -1e30f;
                if (c + 1 > qr1) sc[nt][3] = -1e30f;
            }
        }

        float mx0 = -1e30f, mx1 = -1e30f;
#pragma unroll
        for (int nt = 0; nt < 8; nt++) {
            mx0 = fmaxf(mx0, fmaxf(sc[nt][0], sc[nt][1]));
            mx1 = fmaxf(mx1, fmaxf(sc[nt][2], sc[nt][3]));
        }
        mx0 = fmaxf(mx0, __shfl_xor_sync(0xffffffffu, mx0, 1));
        mx0 = fmaxf(mx0, __shfl_xor_sync(0xffffffffu, mx0, 2));
        mx1 = fmaxf(mx1, __shfl_xor_sync(0xffffffffu, mx1, 1));
        mx1 = fmaxf(mx1, __shfl_xor_sync(0xffffffffu, mx1, 2));
        float mnew0 = fmaxf(m0, mx0);
        float mnew1 = fmaxf(m1, mx1);
        float corr0 = __expf(m0 - mnew0);
        float corr1 = __expf(m1 - mnew1);
        m0 = mnew0; m1 = mnew1;

        float sum0 = 0.f, sum1 = 0.f;
#pragma unroll
        for (int nt = 0; nt < 8; nt++) {
            float p00 = __expf(sc[nt][0] - mnew0);
            float p01 = __expf(sc[nt][1] - mnew0);
            float p10 = __expf(sc[nt][2] - mnew1);
            float p11 = __expf(sc[nt][3] - mnew1);
            sum0 += p00 + p01;
            sum1 += p10 + p11;
            int c = nt * 8 + 2 * t;
            uint32_t H, L;
            split2(p00, p01, H, L);
            *(uint32_t*)&Phi[r0 * PSTR + c] = H;
            *(uint32_t*)&Plo[r0 * PSTR + c] = L;
            split2(p10, p11, H, L);
            *(uint32_t*)&Phi[(r0 + 8) * PSTR + c] = H;
            *(uint32_t*)&Plo[(r0 + 8) * PSTR + c] = L;
        }
        sum0 += __shfl_xor_sync(0xffffffffu, sum0, 1);
        sum0 += __shfl_xor_sync(0xffffffffu, sum0, 2);
        sum1 += __shfl_xor_sync(0xffffffffu, sum1, 1);
        sum1 += __shfl_xor_sync(0xffffffffu, sum1, 2);
        l0 = l0 * corr0 + sum0;
        l1 = l1 * corr1 + sum1;

#pragma unroll
        for (int nt = 0; nt < 16; nt++) {
            oc[nt][0] *= corr0; oc[nt][1] *= corr0;
            oc[nt][2] *= corr1; oc[nt][3] *= corr1;
        }
        __syncwarp();

#pragma unroll
        for (int kk = 0; kk < 4; kk++) {
            uint32_t ph[4], pl[4];
            ldsm_x4(ph, smb + phoff + kk * 32);
            ldsm_x4(pl, smb + ploff + kk * 32);
#pragma unroll
            for (int vj = 0; vj < 8; vj++) {
                uint32_t vh4[4], vl4[4];
                ldsm_x4_t(vh4, smb + sbase + 2 * PLN * 2 + voff_rel[vj] + kk * 16 * VSTR * 2);
                ldsm_x4_t(vl4, smb + sbase + 3 * PLN * 2 + voff_rel[vj] + kk * 16 * VSTR * 2);
#pragma unroll
                for (int hh = 0; hh < 2; hh++) {
                    const int nt = 2 * vj + hh;
                    mma_f16(oc[nt], ph, &vh4[2 * hh]);
                    mma_f16(oc[nt], pl, &vh4[2 * hh]);
                    mma_f16(oc[nt], ph, &vl4[2 * hh]);
                }
            }
        }
        __syncthreads();
    }

    float linv0 = 1.f / l0;
    float linv1 = 1.f / l1;
    __half* Og = g_Oh + ((long)(b * TSEQ + q0)) * DIMC + h * DH;
#pragma unroll
    for (int nt = 0; nt < 16; nt++) {
        int c = nt * 8 + 2 * t;
        *(__half2*)&Og[(long)r0 * DIMC + c] =
            __floats2half2_rn(oc[nt][0] * linv0, oc[nt][1] * linv0);
        *(__half2*)&Og[(long)(r0 + 8) * DIMC + c] =
            __floats2half2_rn(oc[nt][2] * linv1, oc[nt][3] * linv1);
    }
}

// =====================================================================
// launch
// =====================================================================
extern "C" void kernel_launch(void* const* d_in, const int* in_sizes, int n_in,
                              void* d_out, int out_size) {
    const float* X  = (const float*)d_in[0];
    const float* Wq = (const float*)d_in[1];
    const float* Wk = (const float*)d_in[2];
    const float* Wv = (const float*)d_in[3];
    const float* Wo = (const float*)d_in[4];
    float* out = (float*)d_out;

    float  *QKVp;
    __half *Xh, *Wh, *Woh, *Oh;
    cudaGetSymbolAddress((void**)&QKVp, g_QKV);
    cudaGetSymbolAddress((void**)&Xh,  g_Xh);
    cudaGetSymbolAddress((void**)&Wh,  g_Wh);
    cudaGetSymbolAddress((void**)&Woh, g_Woh);
    cudaGetSymbolAddress((void**)&Oh,  g_Oh);

    cudaFuncSetAttribute(gemm_f16, cudaFuncAttributeMaxDynamicSharedMemorySize,
                         GEMM_SMEM_BYTES);
    cudaFuncSetAttribute(flash_tc, cudaFuncAttributeMaxDynamicSharedMemorySize,
                         FLASH_BYTES);

    rope_table<<<(TSEQ * 64 + 255) / 256, 256>>>();

    {
        int n4x = (BT * DIMC) / 4;
        pack_w<<<(n4x + 255) / 256, 256>>>(X, Xh, DIMC, 0, DIMC, n4x);
        int n4q = (DIMC * DIMC) / 4;
        pack_w<<<(n4q + 255) / 256, 256>>>(Wq, Wh, DIMC, 0, QKVN, n4q);
        int n4k = (DIMC * 1024) / 4;
        pack_w<<<(n4k + 255) / 256, 256>>>(Wk, Wh, 1024, KOFF, QKVN, n4k);
        pack_w<<<(n4k + 255) / 256, 256>>>(Wv, Wh, 1024, VOFF, QKVN, n4k);
        pack_w<<<(n4q + 255) / 256, 256>>>(Wo, Woh, DIMC, 0, DIMC, n4q);
    }

    gemm_f16<<<dim3(QKVN / 128, BT / 128), 256, GEMM_SMEM_BYTES>>>(Xh, Wh, QKVp, BT, QKVN, DIMC);

    {
        int total = BT * 8 * 16;
        split_kv<<<(total + 255) / 256, 256>>>(total);
    }

    flash_tc<<<dim3(TSEQ / 128, BB * NH), 256, FLASH_BYTES>>>();

    gemm_f16<<<dim3(DIMC / 128, BT / 128), 256, GEMM_SMEM_BYTES>>>(Oh, Woh, out, BT, DIMC, DIMC);
}

// round 16
// speedup vs baseline: 1.1733x; 1.0002x over previous
#include <cuda_runtime.h>
#include <cuda_fp16.h>
#include <math.h>
#include <stdint.h>

#define DIMC   4096
#define NH     32
#define NKV    8
#define DH     128
#define BB     2
#define TSEQ   2048
#define BT     (BB * TSEQ)
#define QKVN   6144
#define KOFF   4096
#define VOFF   5120
#define KVDIM  1024

__device__ float  g_QKV[BT * QKVN];
__device__ __half g_Xh [BT * DIMC];
__device__ __half g_Wh [DIMC * QKVN];
__device__ __half g_Woh[DIMC * DIMC];
__device__ __half g_Oh [BT * DIMC];
__device__ __half g_Khi[BT * KVDIM];
__device__ __half g_Klo[BT * KVDIM];
__device__ __half g_Vhi[BT * KVDIM];
__device__ __half g_Vlo[BT * KVDIM];
__device__ float  g_cos[TSEQ * 64];
__device__ float  g_sin[TSEQ * 64];

// ---------------- helpers ----------------
__device__ __forceinline__ void mma_f16(float* c, const uint32_t* a, const uint32_t* b) {
    asm volatile(
        "mma.sync.aligned.m16n8k16.row.col.f32.f16.f16.f32 "
        "{%0,%1,%2,%3}, {%4,%5,%6,%7}, {%8,%9}, {%0,%1,%2,%3};"
        : "+f"(c[0]), "+f"(c[1]), "+f"(c[2]), "+f"(c[3])
        : "r"(a[0]), "r"(a[1]), "r"(a[2]), "r"(a[3]), "r"(b[0]), "r"(b[1]));
}
__device__ __forceinline__ void cpasync16(uint32_t dst, const void* src) {
    asm volatile("cp.async.cg.shared.global [%0], [%1], 16;" :: "r"(dst), "l"(src));
}
__device__ __forceinline__ void ldsm_x4(uint32_t* r, uint32_t addr) {
    asm volatile("ldmatrix.sync.aligned.m8n8.x4.shared.b16 {%0,%1,%2,%3}, [%4];"
                 : "=r"(r[0]), "=r"(r[1]), "=r"(r[2]), "=r"(r[3]) : "r"(addr));
}
__device__ __forceinline__ void ldsm_x4_t(uint32_t* r, uint32_t addr) {
    asm volatile("ldmatrix.sync.aligned.m8n8.x4.trans.shared.b16 {%0,%1,%2,%3}, [%4];"
                 : "=r"(r[0]), "=r"(r[1]), "=r"(r[2]), "=r"(r[3]) : "r"(addr));
}
__device__ __forceinline__ void split2(float a, float b, uint32_t& hi, uint32_t& lo) {
    __half ha = __float2half_rn(a), hb = __float2half_rn(b);
    __half la = __float2half_rn(a - __half2float(ha));
    __half lb = __float2half_rn(b - __half2float(hb));
    __half2 H = __halves2half2(ha, hb), L = __halves2half2(la, lb);
    hi = *(uint32_t*)&H; lo = *(uint32_t*)&L;
}

__global__ void pack_w(const float* __restrict__ src, __half* __restrict__ dst,
                       int w, int coff, int dstr, int n4) {
    int i = blockIdx.x * 256 + threadIdx.x;
    if (i >= n4) return;
    int idx = i * 4;
    int r = idx / w, c = idx % w;
    float4 v = *(const float4*)(src + idx);
    __half2* p = (__half2*)(dst + (long)r * dstr + coff + c);
    p[0] = __floats2half2_rn(v.x, v.y);
    p[1] = __floats2half2_rn(v.z, v.w);
}

// split K/V into fp16 hi/lo planes; K rope applied inline.
__global__ void split_kv(int total) {
    int i = blockIdx.x * 256 + threadIdx.x;
    if (i >= total) return;
    int d4 = i & 15;
    int hd = (i >> 4) & 7;
    int bt = i >> 7;
    int tok = bt & (TSEQ - 1);
    int dlo = d4 * 4;
    const float* base = g_QKV + (long)bt * QKVN;
    long o = (long)bt * KVDIM + hd * 128;

    float4 kL = *(const float4*)(base + KOFF + hd * 128 + dlo);
    float4 kH = *(const float4*)(base + KOFF + hd * 128 + dlo + 64);
    float4 cs = *(const float4*)(g_cos + tok * 64 + dlo);
    float4 sn = *(const float4*)(g_sin + tok * 64 + dlo);
    float4 oL, oH;
    oL.x = kL.x * cs.x - kH.x * sn.x;  oH.x = kL.x * sn.x + kH.x * cs.x;
    oL.y = kL.y * cs.y - kH.y * sn.y;  oH.y = kL.y * sn.y + kH.y * cs.y;
    oL.z = kL.z * cs.z - kH.z * sn.z;  oH.z = kL.z * sn.z + kH.z * cs.z;
    oL.w = kL.w * cs.w - kH.w * sn.w;  oH.w = kL.w * sn.w + kH.w * cs.w;

    uint32_t h01, l01, h23, l23;
    split2(oL.x, oL.y, h01, l01); split2(oL.z, oL.w, h23, l23);
    *(uint2*)&g_Khi[o + dlo] = make_uint2(h01, h23);
    *(uint2*)&g_Klo[o + dlo] = make_uint2(l01, l23);
    split2(oH.x, oH.y, h01, l01); split2(oH.z, oH.w, h23, l23);
    *(uint2*)&g_Khi[o + dlo + 64] = make_uint2(h01, h23);
    *(uint2*)&g_Klo[o + dlo + 64] = make_uint2(l01, l23);

    float4 vL = *(const float4*)(base + VOFF + hd * 128 + dlo);
    float4 vH = *(const float4*)(base + VOFF + hd * 128 + dlo + 64);
    split2(vL.x, vL.y, h01, l01); split2(vL.z, vL.w, h23, l23);
    *(uint2*)&g_Vhi[o + dlo] = make_uint2(h01, h23);
    *(uint2*)&g_Vlo[o + dlo] = make_uint2(l01, l23);
    split2(vH.x, vH.y, h01, l01); split2(vH.z, vH.w, h23, l23);
    *(uint2*)&g_Vhi[o + dlo + 64] = make_uint2(h01, h23);
    *(uint2*)&g_Vlo[o + dlo + 64] = make_uint2(l01, l23);
}

// =====================================================================
// FP16 GEMM v4: CTA 128x128, warp tile 64x32, BK=64, TRIPLE-buffered
// cp.async pipeline, ONE barrier per k-tile, 2 CTAs/SM.
// Same ascending-k order -> bit-identical C.
// =====================================================================
#define GBK   64
#define ASTR  72    // halves; 144 B row ≡ 16 mod 128 -> conflict-free ldsm
#define BSTR  136   // halves; 272 B row ≡ 16 mod 128
#define ABUF  (128 * ASTR)
#define BBUF  (GBK * BSTR)
#define GEMM_SMEM_BYTES (3 * (ABUF + BBUF) * 2)   // 107520

__global__ __launch_bounds__(256) void gemm_f16(const __half* __restrict__ A,
                                                const __half* __restrict__ B,
                                                float* __restrict__ C,
                                                int M, int N, int K) {
    extern __shared__ __half hsm[];
    __half* As = hsm;                      // [3][128][ASTR]
    __half* Bs = hsm + 3 * ABUF;           // [3][GBK][BSTR]

    const int tid  = threadIdx.x;
    const int brow = blockIdx.y * 128;
    const int bcol = blockIdx.x * 128;
    const int wid  = tid >> 5, lane = tid & 31;
    const int g    = lane >> 2, t = lane & 3;
    const int m_base = (wid & 1) * 64;
    const int n_base = (wid >> 1) * 32;

    const int xr8 = lane & 15;
    const int xc8 = (lane >> 4) * 8;
    const uint32_t sAb = (uint32_t)__cvta_generic_to_shared(As);
    const uint32_t sBb = (uint32_t)__cvta_generic_to_shared(Bs);
    uint32_t aoff[4];
#pragma unroll
    for (int mi = 0; mi < 4; mi++)
        aoff[mi] = ((m_base + 16 * mi + xr8) * ASTR + xc8) * 2;
    uint32_t boff[2];
#pragma unroll
    for (int nj = 0; nj < 2; nj++)
        boff[nj] = (((lane & 7) + ((lane >> 3) & 1) * 8) * BSTR + n_base + nj * 16 + xc8) * 2;

    float c[4][4][4];
#pragma unroll
    for (int mi = 0; mi < 4; mi++)
#pragma unroll
        for (int ni = 0; ni < 4; ni++)
#pragma unroll
            for (int r = 0; r < 4; r++) c[mi][ni][r] = 0.f;

    auto load_tile = [&](int s, int k0) {
        __half* as = As + s * ABUF;
        __half* bs = Bs + s * BBUF;
#pragma unroll
        for (int it = 0; it < 4; it++) {
            int chunk = it * 256 + tid;        // A: 1024 chunks of 8 halves
            int r = chunk >> 3, c8 = (chunk & 7) * 8;
            cpasync16((uint32_t)__cvta_generic_to_shared(&as[r * ASTR + c8]),
                      A + (long)(brow + r) * K + k0 + c8);
        }
#pragma unroll
        for (int it = 0; it < 4; it++) {
            int chunk = it * 256 + tid;        // B: 1024 chunks
            int r = chunk >> 4, c8 = (chunk & 15) * 8;
            cpasync16((uint32_t)__cvta_generic_to_shared(&bs[r * BSTR + c8]),
                      B + (long)(k0 + r) * N + bcol + c8);
        }
        asm volatile("cp.async.commit_group;");
    };

    const int KT = K / GBK;
    load_tile(0, 0);
    load_tile(1, GBK);

    int s = 0;
    for (int kt = 0; kt < KT; kt++) {
        if (kt + 1 < KT) {
            asm volatile("cp.async.wait_group 1;");
        } else {
            asm volatile("cp.async.wait_group 0;");
        }
        __syncthreads();   // tile kt visible; all warps done with buffer (kt+2)%3's old data

        if (kt + 2 < KT) {
            int sn = s + 2; if (sn >= 3) sn -= 3;
            load_tile(sn, (kt + 2) * GBK);
        }

        const uint32_t ab = sAb + (uint32_t)(s * ABUF * 2);
        const uint32_t bb = sBb + (uint32_t)(s * BBUF * 2);
#pragma unroll
        for (int j = 0; j < 4; j++) {          // four k16 steps (ascending k)
            uint32_t af[4][4], bq[2][4];
#pragma unroll
            for (int mi = 0; mi < 4; mi++)
                ldsm_x4(af[mi], ab + aoff[mi] + j * 32);
#pragma unroll
            for (int nj = 0; nj < 2; nj++)
                ldsm_x4_t(bq[nj], bb + boff[nj] + j * 16 * BSTR * 2);
#pragma unroll
            for (int mi = 0; mi < 4; mi++)
#pragma unroll
                for (int nj = 0; nj < 2; nj++) {
                    mma_f16(c[mi][2 * nj + 0], af[mi], &bq[nj][0]);
                    mma_f16(c[mi][2 * nj + 1], af[mi], &bq[nj][2]);
                }
        }
        if (++s >= 3) s -= 3;
    }

#pragma unroll
    for (int mi = 0; mi < 4; mi++) {
#pragma unroll
        for (int ni = 0; ni < 4; ni++) {
            long row = brow + m_base + 16 * mi + g;
            int  col = bcol + n_base + 8 * ni + 2 * t;
            *(float2*)&C[row * N + col]       = make_float2(c[mi][ni][0], c[mi][ni][1]);
            *(float2*)&C[(row + 8) * N + col] = make_float2(c[mi][ni][2], c[mi][ni][3]);
        }
    }
}

// =====================================================================
// RoPE table
// =====================================================================
__global__ void rope_table() {
    int idx = blockIdx.x * 256 + threadIdx.x;
    if (idx >= TSEQ * 64) return;
    int d = idx & 63, t = idx >> 6;
    double inv = pow(10000.0, -(double)d / 64.0);
    double ang = (double)t * inv;
    g_cos[idx] = (float)cos(ang);
    g_sin[idx] = (float)sin(ang);
}

// =====================================================================
// Flash attention v4 (R14/R15-exact)
// =====================================================================
#define KSTR 136
#define VSTR 136
#define PSTR 72
#define PLN   (64 * KSTR)
#define BUFH  (4 * PLN)
#define PHI_H (2 * BUFH)
#define PLO_H (PHI_H + 128 * PSTR)
#define FLASH_BYTES ((PLO_H + 128 * PSTR) * 2)

__global__ __launch_bounds__(256, 1) void flash_tc() {
    extern __shared__ __half hs[];
    __half* Phi = hs + PHI_H;
    __half* Plo = hs + PLO_H;

    const int tid = threadIdx.x;
    const int qt  = (int)(gridDim.x - 1 - blockIdx.x);
    const int bh  = blockIdx.y;
    const int b   = bh >> 5;
    const int h   = bh & 31;
    const int kvh = h >> 2;
    const int q0  = qt * 128;
    const int lane = tid & 31, wid = tid >> 5;
    const int g = lane >> 2, t = lane & 3;
    const int wm = wid;
    const int r0 = wm * 16 + g;

    const uint32_t smb = (uint32_t)__cvta_generic_to_shared(hs);
    const int n_loc  = (lane & 7) + ((lane >> 4) << 3);
    const int k_half = (lane >> 3) & 1;
    uint32_t koff_rel[4];
#pragma unroll
    for (int j = 0; j < 4; j++)
        koff_rel[j] = ((j * 16 + n_loc) * KSTR + k_half * 8) * 2;
    const int xr  = lane & 15;
    const int xc8 = (lane >> 4) * 8;
    const uint32_t phoff = (PHI_H + (wm * 16 + xr) * PSTR + xc8) * 2;
    const uint32_t ploff = (PLO_H + (wm * 16 + xr) * PSTR + xc8) * 2;
    const int xrv = (lane & 7) + ((lane >> 3) & 1) * 8;
    uint32_t voff_rel[8];
#pragma unroll
    for (int vj = 0; vj < 8; vj++)
        voff_rel[vj] = (xrv * VSTR + vj * 16 + xc8) * 2;

    const float scale = 0.0883883476483184f;
    uint32_t qhi[8][4], qlo[8][4];
    {
        const float* Qg = g_QKV + ((long)(b * TSEQ + q0)) * QKVN + h * DH;
        float2 raw[8][4];
#pragma unroll
        for (int kk = 0; kk < 8; kk++) {
            const int c = kk * 16 + 2 * t;
            raw[kk][0] = *(const float2*)&Qg[(long)r0 * QKVN + c];
            raw[kk][1] = *(const float2*)&Qg[(long)(r0 + 8) * QKVN + c];
            raw[kk][2] = *(const float2*)&Qg[(long)r0 * QKVN + c + 8];
            raw[kk][3] = *(const float2*)&Qg[(long)(r0 + 8) * QKVN + c + 8];
        }
        const int tok0 = q0 + r0, tok1 = tok0 + 8;
#pragma unroll
        for (int kk = 0; kk < 4; kk++) {
            const int dbase = kk * 16 + 2 * t;
#pragma unroll
            for (int si = 0; si < 4; si++) {
                const int tok  = (si & 1) ? tok1 : tok0;
                const int doff = (si & 2) ? 8 : 0;
                float2 cc = *(const float2*)&g_cos[tok * 64 + dbase + doff];
                float2 ss = *(const float2*)&g_sin[tok * 64 + dbase + doff];
                float2 lo2 = raw[kk][si], hi2 = raw[kk + 4][si];
                float olx = lo2.x * cc.x - hi2.x * ss.x;
                float ohx = lo2.x * ss.x + hi2.x * cc.x;
                float oly = lo2.y * cc.y - hi2.y * ss.y;
                float ohy = lo2.y * ss.y + hi2.y * cc.y;
                split2(olx * scale, oly * scale, qhi[kk][si],     qlo[kk][si]);
                split2(ohx * scale, ohy * scale, qhi[kk + 4][si], qlo[kk + 4][si]);
            }
        }
    }
    float m0 = -1e30f, m1 = -1e30f, l0 = 0.f, l1 = 0.f;

    const __half* Kh = g_Khi + (long)(b * TSEQ) * KVDIM + kvh * DH;
    const __half* Kl = g_Klo + (long)(b * TSEQ) * KVDIM + kvh * DH;
    const __half* Vh = g_Vhi + (long)(b * TSEQ) * KVDIM + kvh * DH;
    const __half* Vl = g_Vlo + (long)(b * TSEQ) * KVDIM + kvh * DH;

    auto issue_tile = [&](int s, int k0) {
#pragma unroll
        for (int it = 0; it < 4; it++) {
            int chunk = it * 256 + tid;
            int row = chunk >> 4;
            int c8  = (chunk & 15) * 8;
            long go = (long)(k0 + row) * KVDIM + c8;
            uint32_t sb = smb + (uint32_t)(s * BUFH * 2 + (row * KSTR + c8) * 2);
            cpasync16(sb,               Kh + go);
            cpasync16(sb + PLN * 2,     Kl + go);
            cpasync16(sb + 2 * PLN * 2, Vh + go);
            cpasync16(sb + 3 * PLN * 2, Vl + go);
        }
    };

    float oc[16][4];
#pragma unroll
    for (int nt = 0; nt < 16; nt++)
#pragma unroll
        for (int r = 0; r < 4; r++) oc[nt][r] = 0.f;

    const int KT = 2 * qt + 2;
    issue_tile(0, 0);
    asm volatile("cp.async.commit_group;");

    for (int kt = 0; kt < KT; kt++) {
        const int s = kt & 1;
        if (kt + 1 < KT) {
            issue_tile(s ^ 1, (kt + 1) * 64);
            asm volatile("cp.async.commit_group;");
            asm volatile("cp.async.wait_group 1;");
        } else {
            asm volatile("cp.async.wait_group 0;");
        }
        __syncthreads();

        const uint32_t sbase = (uint32_t)(s * BUFH * 2);
        const int k0 = kt * 64;

        float sc[8][4];
#pragma unroll
        for (int nt = 0; nt < 8; nt++)
#pragma unroll
            for (int r = 0; r < 4; r++) sc[nt][r] = 0.f;

#pragma unroll
        for (int kk = 0; kk < 8; kk++) {
            uint32_t kh[4][4], kl[4][4];
#pragma unroll
            for (int j = 0; j < 4; j++) {
                ldsm_x4(kh[j], smb + sbase + koff_rel[j] + kk * 32);
                ldsm_x4(kl[j], smb + sbase + PLN * 2 + koff_rel[j] + kk * 32);
            }
#pragma unroll
            for (int j = 0; j < 4; j++)
#pragma unroll
                for (int hh = 0; hh < 2; hh++) {
                    const int nt = 2 * j + hh;
                    mma_f16(sc[nt], qhi[kk], &kh[j][2 * hh]);
                    mma_f16(sc[nt], qlo[kk], &kh[j][2 * hh]);
                    mma_f16(sc[nt], qhi[kk], &kl[j][2 * hh]);
                }
        }

        if (kt >= 2 * qt) {
            const int qr0 = q0 + r0, qr1 = q0 + r0 + 8;
#pragma unroll
            for (int nt = 0; nt < 8; nt++) {
                int c = k0 + nt * 8 + 2 * t;
                if (c     > qr0) sc[nt][0] = -1e30f;
                if (c + 1 > qr0) sc[nt][1] = -1e30f;
                if (c     > qr1) sc[nt][2] = -1e30f;
                if (c + 1 > qr1) sc[nt][3] = -1e30f;
            }
        }

        float mx0 = -1e30f, mx1 = -1e30f;
#pragma unroll
        for (int nt = 0; nt < 8; nt++) {
            mx0 = fmaxf(mx0, fmaxf(sc[nt][0], sc[nt][1]));
            mx1 = fmaxf(mx1, fmaxf(sc[nt][2], sc[nt][3]));
        }
        mx0 = fmaxf(mx0, __shfl_xor_sync(0xffffffffu, mx0, 1));
        mx0 = fmaxf(mx0, __shfl_xor_sync(0xffffffffu, mx0, 2));
        mx1 = fmaxf(mx1, __shfl_xor_sync(0xffffffffu, mx1, 1));
        mx1 = fmaxf(mx1, __shfl_xor_sync(0xffffffffu, mx1, 2));
        float mnew0 = fmaxf(m0, mx0);
        float mnew1 = fmaxf(m1, mx1);
        float corr0 = __expf(m0 - mnew0);
        float corr1 = __expf(m1 - mnew1);
        m0 = mnew0; m1 = mnew1;

        float sum0 = 0.f, sum1 = 0.f;
#pragma unroll
        for (int nt = 0; nt < 8; nt++) {
            float p00 = __expf(sc[nt][0] - mnew0);
            float p01 = __expf(sc[nt][1] - mnew0);
            float p10 = __expf(sc[nt][2] - mnew1);
            float p11 = __expf(sc[nt][3] - mnew1);
            sum0 += p00 + p01;
            sum1 += p10 + p11;
            int c = nt * 8 + 2 * t;
            uint32_t H, L;
            split2(p00, p01, H, L);
            *(uint32_t*)&Phi[r0 * PSTR + c] = H;
            *(uint32_t*)&Plo[r0 * PSTR + c] = L;
            split2(p10, p11, H, L);
            *(uint32_t*)&Phi[(r0 + 8) * PSTR + c] = H;
            *(uint32_t*)&Plo[(r0 + 8) * PSTR + c] = L;
        }
        sum0 += __shfl_xor_sync(0xffffffffu, sum0, 1);
        sum0 += __shfl_xor_sync(0xffffffffu, sum0, 2);
        sum1 += __shfl_xor_sync(0xffffffffu, sum1, 1);
        sum1 += __shfl_xor_sync(0xffffffffu, sum1, 2);
        l0 = l0 * corr0 + sum0;
        l1 = l1 * corr1 + sum1;

#pragma unroll
        for (int nt = 0; nt < 16; nt++) {
            oc[nt][0] *= corr0; oc[nt][1] *= corr0;
            oc[nt][2] *= corr1; oc[nt][3] *= corr1;
        }
        __syncwarp();

#pragma unroll
        for (int kk = 0; kk < 4; kk++) {
            uint32_t ph[4], pl[4];
            ldsm_x4(ph, smb + phoff + kk * 32);
            ldsm_x4(pl, smb + ploff + kk * 32);
#pragma unroll
            for (int vj = 0; vj < 8; vj++) {
                uint32_t vh4[4], vl4[4];
                ldsm_x4_t(vh4, smb + sbase + 2 * PLN * 2 + voff_rel[vj] + kk * 16 * VSTR * 2);
                ldsm_x4_t(vl4, smb + sbase + 3 * PLN * 2 + voff_rel[vj] + kk * 16 * VSTR * 2);
#pragma unroll
                for (int hh = 0; hh < 2; hh++) {
                    const int nt = 2 * vj + hh;
                    mma_f16(oc[nt], ph, &vh4[2 * hh]);
                    mma_f16(oc[nt], pl, &vh4[2 * hh]);
                    mma_f16(oc[nt], ph, &vl4[2 * hh]);
                }
            }
        }
        __syncthreads();
    }

    float linv0 = 1.f / l0;
    float linv1 = 1.f / l1;
    __half* Og = g_Oh + ((long)(b * TSEQ + q0)) * DIMC + h * DH;
#pragma unroll
    for (int nt = 0; nt < 16; nt++) {
        int c = nt * 8 + 2 * t;
        *(__half2*)&Og[(long)r0 * DIMC + c] =
            __floats2half2_rn(oc[nt][0] * linv0, oc[nt][1] * linv0);
        *(__half2*)&Og[(long)(r0 + 8) * DIMC + c] =
            __floats2half2_rn(oc[nt][2] * linv1, oc[nt][3] * linv1);
    }
}

// =====================================================================
// launch
// =====================================================================
extern "C" void kernel_launch(void* const* d_in, const int* in_sizes, int n_in,
                              void* d_out, int out_size) {
    const float* X  = (const float*)d_in[0];
    const float* Wq = (const float*)d_in[1];
    const float* Wk = (const float*)d_in[2];
    const float* Wv = (const float*)d_in[3];
    const float* Wo = (const float*)d_in[4];
    float* out = (float*)d_out;

    float  *QKVp;
    __half *Xh, *Wh, *Woh, *Oh;
    cudaGetSymbolAddress((void**)&QKVp, g_QKV);
    cudaGetSymbolAddress((void**)&Xh,  g_Xh);
    cudaGetSymbolAddress((void**)&Wh,  g_Wh);
    cudaGetSymbolAddress((void**)&Woh, g_Woh);
    cudaGetSymbolAddress((void**)&Oh,  g_Oh);

    cudaFuncSetAttribute(gemm_f16, cudaFuncAttributeMaxDynamicSharedMemorySize,
                         GEMM_SMEM_BYTES);
    cudaFuncSetAttribute(flash_tc, cudaFuncAttributeMaxDynamicSharedMemorySize,
                         FLASH_BYTES);

    rope_table<<<(TSEQ * 64 + 255) / 256, 256>>>();

    {
        int n4x = (BT * DIMC) / 4;
        pack_w<<<(n4x + 255) / 256, 256>>>(X, Xh, DIMC, 0, DIMC, n4x);
        int n4q = (DIMC * DIMC) / 4;
        pack_w<<<(n4q + 255) / 256, 256>>>(Wq, Wh, DIMC, 0, QKVN, n4q);
        int n4k = (DIMC * 1024) / 4;
        pack_w<<<(n4k + 255) / 256, 256>>>(Wk, Wh, 1024, KOFF, QKVN, n4k);
        pack_w<<<(n4k + 255) / 256, 256>>>(Wv, Wh, 1024, VOFF, QKVN, n4k);
        pack_w<<<(n4q + 255) / 256, 256>>>(Wo, Woh, DIMC, 0, DIMC, n4q);
    }

    gemm_f16<<<dim3(QKVN / 128, BT / 128), 256, GEMM_SMEM_BYTES>>>(Xh, Wh, QKVp, BT, QKVN, DIMC);

    {
        int total = BT * 8 * 16;
        split_kv<<<(total + 255) / 256, 256>>>(total);
    }

    flash_tc<<<dim3(TSEQ / 128, BB * NH), 256, FLASH_BYTES>>>();

    gemm_f16<<<dim3(DIMC / 128, BT / 128), 256, GEMM_SMEM_BYTES>>>(Oh, Woh, out, BT, DIMC, DIMC);
}

// round 17
// speedup vs baseline: 1.1816x; 1.0070x over previous
#include <cuda_runtime.h>
#include <cuda_fp16.h>
#include <math.h>
#include <stdint.h>

#define DIMC   4096
#define NH     32
#define NKV    8
#define DH     128
#define BB     2
#define TSEQ   2048
#define BT     (BB * TSEQ)
#define QKVN   6144
#define KOFF   4096
#define VOFF   5120
#define KVDIM  1024

__device__ float  g_QKV[BT * QKVN];
__device__ __half g_Xh [BT * DIMC];
__device__ __half g_Wh [DIMC * QKVN];
__device__ __half g_Woh[DIMC * DIMC];
__device__ __half g_Oh [BT * DIMC];
__device__ __half g_Khi[BT * KVDIM];
__device__ __half g_Klo[BT * KVDIM];
__device__ __half g_Vhi[BT * KVDIM];
__device__ __half g_Vlo[BT * KVDIM];
__device__ float  g_cos[TSEQ * 64];
__device__ float  g_sin[TSEQ * 64];

// ---------------- helpers ----------------
__device__ __forceinline__ void mma_f16(float* c, const uint32_t* a, const uint32_t* b) {
    asm volatile(
        "mma.sync.aligned.m16n8k16.row.col.f32.f16.f16.f32 "
        "{%0,%1,%2,%3}, {%4,%5,%6,%7}, {%8,%9}, {%0,%1,%2,%3};"
        : "+f"(c[0]), "+f"(c[1]), "+f"(c[2]), "+f"(c[3])
        : "r"(a[0]), "r"(a[1]), "r"(a[2]), "r"(a[3]), "r"(b[0]), "r"(b[1]));
}
__device__ __forceinline__ void cpasync16(uint32_t dst, const void* src) {
    asm volatile("cp.async.cg.shared.global [%0], [%1], 16;" :: "r"(dst), "l"(src));
}
__device__ __forceinline__ void ldsm_x4(uint32_t* r, uint32_t addr) {
    asm volatile("ldmatrix.sync.aligned.m8n8.x4.shared.b16 {%0,%1,%2,%3}, [%4];"
                 : "=r"(r[0]), "=r"(r[1]), "=r"(r[2]), "=r"(r[3]) : "r"(addr));
}
__device__ __forceinline__ void ldsm_x4_t(uint32_t* r, uint32_t addr) {
    asm volatile("ldmatrix.sync.aligned.m8n8.x4.trans.shared.b16 {%0,%1,%2,%3}, [%4];"
                 : "=r"(r[0]), "=r"(r[1]), "=r"(r[2]), "=r"(r[3]) : "r"(addr));
}
__device__ __forceinline__ void split2(float a, float b, uint32_t& hi, uint32_t& lo) {
    __half ha = __float2half_rn(a), hb = __float2half_rn(b);
    __half la = __float2half_rn(a - __half2float(ha));
    __half lb = __float2half_rn(b - __half2float(hb));
    __half2 H = __halves2half2(ha, hb), L = __halves2half2(la, lb);
    hi = *(uint32_t*)&H; lo = *(uint32_t*)&L;
}

__global__ void pack_w(const float* __restrict__ src, __half* __restrict__ dst,
                       int w, int coff, int dstr, int n4) {
    int i = blockIdx.x * 256 + threadIdx.x;
    if (i >= n4) return;
    int idx = i * 4;
    int r = idx / w, c = idx % w;
    float4 v = *(const float4*)(src + idx);
    __half2* p = (__half2*)(dst + (long)r * dstr + coff + c);
    p[0] = __floats2half2_rn(v.x, v.y);
    p[1] = __floats2half2_rn(v.z, v.w);
}

// split K/V into fp16 hi/lo planes; K rope applied inline.
__global__ void split_kv(int total) {
    int i = blockIdx.x * 256 + threadIdx.x;
    if (i >= total) return;
    int d4 = i & 15;
    int hd = (i >> 4) & 7;
    int bt = i >> 7;
    int tok = bt & (TSEQ - 1);
    int dlo = d4 * 4;
    const float* base = g_QKV + (long)bt * QKVN;
    long o = (long)bt * KVDIM + hd * 128;

    float4 kL = *(const float4*)(base + KOFF + hd * 128 + dlo);
    float4 kH = *(const float4*)(base + KOFF + hd * 128 + dlo + 64);
    float4 cs = *(const float4*)(g_cos + tok * 64 + dlo);
    float4 sn = *(const float4*)(g_sin + tok * 64 + dlo);
    float4 oL, oH;
    oL.x = kL.x * cs.x - kH.x * sn.x;  oH.x = kL.x * sn.x + kH.x * cs.x;
    oL.y = kL.y * cs.y - kH.y * sn.y;  oH.y = kL.y * sn.y + kH.y * cs.y;
    oL.z = kL.z * cs.z - kH.z * sn.z;  oH.z = kL.z * sn.z + kH.z * cs.z;
    oL.w = kL.w * cs.w - kH.w * sn.w;  oH.w = kL.w * sn.w + kH.w * cs.w;

    uint32_t h01, l01, h23, l23;
    split2(oL.x, oL.y, h01, l01); split2(oL.z, oL.w, h23, l23);
    *(uint2*)&g_Khi[o + dlo] = make_uint2(h01, h23);
    *(uint2*)&g_Klo[o + dlo] = make_uint2(l01, l23);
    split2(oH.x, oH.y, h01, l01); split2(oH.z, oH.w, h23, l23);
    *(uint2*)&g_Khi[o + dlo + 64] = make_uint2(h01, h23);
    *(uint2*)&g_Klo[o + dlo + 64] = make_uint2(l01, l23);

    float4 vL = *(const float4*)(base + VOFF + hd * 128 + dlo);
    float4 vH = *(const float4*)(base + VOFF + hd * 128 + dlo + 64);
    split2(vL.x, vL.y, h01, l01); split2(vL.z, vL.w, h23, l23);
    *(uint2*)&g_Vhi[o + dlo] = make_uint2(h01, h23);
    *(uint2*)&g_Vlo[o + dlo] = make_uint2(l01, l23);
    split2(vH.x, vH.y, h01, l01); split2(vH.z, vH.w, h23, l23);
    *(uint2*)&g_Vhi[o + dlo + 64] = make_uint2(h01, h23);
    *(uint2*)&g_Vlo[o + dlo + 64] = make_uint2(l01, l23);
}

// =====================================================================
// FP16 GEMM v4 (R16-exact): CTA 128x128, warp 64x32, BK=64, triple buffer,
// one barrier per k-tile, 2 CTAs/SM. Bit-identical C.
// =====================================================================
#define GBK   64
#define ASTR  72
#define BSTR  136
#define ABUF  (128 * ASTR)
#define BBUF  (GBK * BSTR)
#define GEMM_SMEM_BYTES (3 * (ABUF + BBUF) * 2)

__global__ __launch_bounds__(256) void gemm_f16(const __half* __restrict__ A,
                                                const __half* __restrict__ B,
                                                float* __restrict__ C,
                                                int M, int N, int K) {
    extern __shared__ __half hsm[];
    __half* As = hsm;
    __half* Bs = hsm + 3 * ABUF;

    const int tid  = threadIdx.x;
    const int brow = blockIdx.y * 128;
    const int bcol = blockIdx.x * 128;
    const int wid  = tid >> 5, lane = tid & 31;
    const int g    = lane >> 2, t = lane & 3;
    const int m_base = (wid & 1) * 64;
    const int n_base = (wid >> 1) * 32;

    const int xr8 = lane & 15;
    const int xc8 = (lane >> 4) * 8;
    const uint32_t sAb = (uint32_t)__cvta_generic_to_shared(As);
    const uint32_t sBb = (uint32_t)__cvta_generic_to_shared(Bs);
    uint32_t aoff[4];
#pragma unroll
    for (int mi = 0; mi < 4; mi++)
        aoff[mi] = ((m_base + 16 * mi + xr8) * ASTR + xc8) * 2;
    uint32_t boff[2];
#pragma unroll
    for (int nj = 0; nj < 2; nj++)
        boff[nj] = (((lane & 7) + ((lane >> 3) & 1) * 8) * BSTR + n_base + nj * 16 + xc8) * 2;

    float c[4][4][4];
#pragma unroll
    for (int mi = 0; mi < 4; mi++)
#pragma unroll
        for (int ni = 0; ni < 4; ni++)
#pragma unroll
            for (int r = 0; r < 4; r++) c[mi][ni][r] = 0.f;

    auto load_tile = [&](int s, int k0) {
        __half* as = As + s * ABUF;
        __half* bs = Bs + s * BBUF;
#pragma unroll
        for (int it = 0; it < 4; it++) {
            int chunk = it * 256 + tid;
            int r = chunk >> 3, c8 = (chunk & 7) * 8;
            cpasync16((uint32_t)__cvta_generic_to_shared(&as[r * ASTR + c8]),
                      A + (long)(brow + r) * K + k0 + c8);
        }
#pragma unroll
        for (int it = 0; it < 4; it++) {
            int chunk = it * 256 + tid;
            int r = chunk >> 4, c8 = (chunk & 15) * 8;
            cpasync16((uint32_t)__cvta_generic_to_shared(&bs[r * BSTR + c8]),
                      B + (long)(k0 + r) * N + bcol + c8);
        }
        asm volatile("cp.async.commit_group;");
    };

    const int KT = K / GBK;
    load_tile(0, 0);
    load_tile(1, GBK);

    int s = 0;
    for (int kt = 0; kt < KT; kt++) {
        if (kt + 1 < KT) {
            asm volatile("cp.async.wait_group 1;");
        } else {
            asm volatile("cp.async.wait_group 0;");
        }
        __syncthreads();

        if (kt + 2 < KT) {
            int sn = s + 2; if (sn >= 3) sn -= 3;
            load_tile(sn, (kt + 2) * GBK);
        }

        const uint32_t ab = sAb + (uint32_t)(s * ABUF * 2);
        const uint32_t bb = sBb + (uint32_t)(s * BBUF * 2);
#pragma unroll
        for (int j = 0; j < 4; j++) {
            uint32_t af[4][4], bq[2][4];
#pragma unroll
            for (int mi = 0; mi < 4; mi++)
                ldsm_x4(af[mi], ab + aoff[mi] + j * 32);
#pragma unroll
            for (int nj = 0; nj < 2; nj++)
                ldsm_x4_t(bq[nj], bb + boff[nj] + j * 16 * BSTR * 2);
#pragma unroll
            for (int mi = 0; mi < 4; mi++)
#pragma unroll
                for (int nj = 0; nj < 2; nj++) {
                    mma_f16(c[mi][2 * nj + 0], af[mi], &bq[nj][0]);
                    mma_f16(c[mi][2 * nj + 1], af[mi], &bq[nj][2]);
                }
        }
        if (++s >= 3) s -= 3;
    }

#pragma unroll
    for (int mi = 0; mi < 4; mi++) {
#pragma unroll
        for (int ni = 0; ni < 4; ni++) {
            long row = brow + m_base + 16 * mi + g;
            int  col = bcol + n_base + 8 * ni + 2 * t;
            *(float2*)&C[row * N + col]       = make_float2(c[mi][ni][0], c[mi][ni][1]);
            *(float2*)&C[(row + 8) * N + col] = make_float2(c[mi][ni][2], c[mi][ni][3]);
        }
    }
}

// =====================================================================
// RoPE table
// =====================================================================
__global__ void rope_table() {
    int idx = blockIdx.x * 256 + threadIdx.x;
    if (idx >= TSEQ * 64) return;
    int d = idx & 63, t = idx >> 6;
    double inv = pow(10000.0, -(double)d / 64.0);
    double ang = (double)t * inv;
    g_cos[idx] = (float)cos(ang);
    g_sin[idx] = (float)sin(ang);
}

// =====================================================================
// Flash attention v5: P stays in registers (C-frag == A-frag layout),
// 3-stage KV cp.async pipeline, ONE barrier per tile. Bit-identical math.
// =====================================================================
#define KSTR 136
#define VSTR 136
#define PLN   (64 * KSTR)
#define BUFH  (4 * PLN)
#define FLASH_BYTES (3 * BUFH * 2)    // 208,896

__global__ __launch_bounds__(256, 1) void flash_tc() {
    extern __shared__ __half hs[];

    const int tid = threadIdx.x;
    const int qt  = (int)(gridDim.x - 1 - blockIdx.x);
    const int bh  = blockIdx.y;
    const int b   = bh >> 5;
    const int h   = bh & 31;
    const int kvh = h >> 2;
    const int q0  = qt * 128;
    const int lane = tid & 31, wid = tid >> 5;
    const int g = lane >> 2, t = lane & 3;
    const int wm = wid;
    const int r0 = wm * 16 + g;

    const uint32_t smb = (uint32_t)__cvta_generic_to_shared(hs);
    const int n_loc  = (lane & 7) + ((lane >> 4) << 3);
    const int k_half = (lane >> 3) & 1;
    uint32_t koff_rel[4];
#pragma unroll
    for (int j = 0; j < 4; j++)
        koff_rel[j] = ((j * 16 + n_loc) * KSTR + k_half * 8) * 2;
    const int xc8 = (lane >> 4) * 8;
    const int xrv = (lane & 7) + ((lane >> 3) & 1) * 8;
    uint32_t voff_rel[8];
#pragma unroll
    for (int vj = 0; vj < 8; vj++)
        voff_rel[vj] = (xrv * VSTR + vj * 16 + xc8) * 2;

    // ---- Q fragments: load raw, rope in registers, scale, split ----
    const float scale = 0.0883883476483184f;
    uint32_t qhi[8][4], qlo[8][4];
    {
        const float* Qg = g_QKV + ((long)(b * TSEQ + q0)) * QKVN + h * DH;
        float2 raw[8][4];
#pragma unroll
        for (int kk = 0; kk < 8; kk++) {
            const int c = kk * 16 + 2 * t;
            raw[kk][0] = *(const float2*)&Qg[(long)r0 * QKVN + c];
            raw[kk][1] = *(const float2*)&Qg[(long)(r0 + 8) * QKVN + c];
            raw[kk][2] = *(const float2*)&Qg[(long)r0 * QKVN + c + 8];
            raw[kk][3] = *(const float2*)&Qg[(long)(r0 + 8) * QKVN + c + 8];
        }
        const int tok0 = q0 + r0, tok1 = tok0 + 8;
#pragma unroll
        for (int kk = 0; kk < 4; kk++) {
            const int dbase = kk * 16 + 2 * t;
#pragma unroll
            for (int si = 0; si < 4; si++) {
                const int tok  = (si & 1) ? tok1 : tok0;
                const int doff = (si & 2) ? 8 : 0;
                float2 cc = *(const float2*)&g_cos[tok * 64 + dbase + doff];
                float2 ss = *(const float2*)&g_sin[tok * 64 + dbase + doff];
                float2 lo2 = raw[kk][si], hi2 = raw[kk + 4][si];
                float olx = lo2.x * cc.x - hi2.x * ss.x;
                float ohx = lo2.x * ss.x + hi2.x * cc.x;
                float oly = lo2.y * cc.y - hi2.y * ss.y;
                float ohy = lo2.y * ss.y + hi2.y * cc.y;
                split2(olx * scale, oly * scale, qhi[kk][si],     qlo[kk][si]);
                split2(ohx * scale, ohy * scale, qhi[kk + 4][si], qlo[kk + 4][si]);
            }
        }
    }
    float m0 = -1e30f, m1 = -1e30f, l0 = 0.f, l1 = 0.f;

    const __half* Kh = g_Khi + (long)(b * TSEQ) * KVDIM + kvh * DH;
    const __half* Kl = g_Klo + (long)(b * TSEQ) * KVDIM + kvh * DH;
    const __half* Vh = g_Vhi + (long)(b * TSEQ) * KVDIM + kvh * DH;
    const __half* Vl = g_Vlo + (long)(b * TSEQ) * KVDIM + kvh * DH;

    auto issue_tile = [&](int s, int k0) {
#pragma unroll
        for (int it = 0; it < 4; it++) {
            int chunk = it * 256 + tid;
            int row = chunk >> 4;
            int c8  = (chunk & 15) * 8;
            long go = (long)(k0 + row) * KVDIM + c8;
            uint32_t sb = smb + (uint32_t)(s * BUFH * 2 + (row * KSTR + c8) * 2);
            cpasync16(sb,               Kh + go);
            cpasync16(sb + PLN * 2,     Kl + go);
            cpasync16(sb + 2 * PLN * 2, Vh + go);
            cpasync16(sb + 3 * PLN * 2, Vl + go);
        }
        asm volatile("cp.async.commit_group;");
    };

    float oc[16][4];
#pragma unroll
    for (int nt = 0; nt < 16; nt++)
#pragma unroll
        for (int r = 0; r < 4; r++) oc[nt][r] = 0.f;

    const int KT = 2 * qt + 2;     // KT >= 2 always
    issue_tile(0, 0);
    issue_tile(1, 64);

    int s = 0;
    for (int kt = 0; kt < KT; kt++) {
        if (kt + 1 < KT) {
            asm volatile("cp.async.wait_group 1;");
        } else {
            asm volatile("cp.async.wait_group 0;");
        }
        __syncthreads();   // tile kt visible; buffer (kt+2)%3's old readers done

        if (kt + 2 < KT) {
            int sn = s + 2; if (sn >= 3) sn -= 3;
            issue_tile(sn, (kt + 2) * 64);
        }

        const uint32_t sbase = (uint32_t)(s * BUFH * 2);
        const int k0 = kt * 64;

        // ---- S = Q K^T ----
        float sc[8][4];
#pragma unroll
        for (int nt = 0; nt < 8; nt++)
#pragma unroll
            for (int r = 0; r < 4; r++) sc[nt][r] = 0.f;

#pragma unroll
        for (int kk = 0; kk < 8; kk++) {
            uint32_t kh[4][4], kl[4][4];
#pragma unroll
            for (int j = 0; j < 4; j++) {
                ldsm_x4(kh[j], smb + sbase + koff_rel[j] + kk * 32);
                ldsm_x4(kl[j], smb + sbase + PLN * 2 + koff_rel[j] + kk * 32);
            }
#pragma unroll
            for (int j = 0; j < 4; j++)
#pragma unroll
                for (int hh = 0; hh < 2; hh++) {
                    const int nt = 2 * j + hh;
                    mma_f16(sc[nt], qhi[kk], &kh[j][2 * hh]);
                    mma_f16(sc[nt], qlo[kk], &kh[j][2 * hh]);
                    mma_f16(sc[nt], qhi[kk], &kl[j][2 * hh]);
                }
        }

        if (kt >= 2 * qt) {
            const int qr0 = q0 + r0, qr1 = q0 + r0 + 8;
#pragma unroll
            for (int nt = 0; nt < 8; nt++) {
                int c = k0 + nt * 8 + 2 * t;
                if (c     > qr0) sc[nt][0] = -1e30f;
                if (c + 1 > qr0) sc[nt][1] = -1e30f;
                if (c     > qr1) sc[nt][2] = -1e30f;
                if (c + 1 > qr1) sc[nt][3] = -1e30f;
            }
        }

        // ---- warp-private online softmax; P stays in registers ----
        float mx0 = -1e30f, mx1 = -1e30f;
#pragma unroll
        for (int nt = 0; nt < 8; nt++) {
            mx0 = fmaxf(mx0, fmaxf(sc[nt][0], sc[nt][1]));
            mx1 = fmaxf(mx1, fmaxf(sc[nt][2], sc[nt][3]));
        }
        mx0 = fmaxf(mx0, __shfl_xor_sync(0xffffffffu, mx0, 1));
        mx0 = fmaxf(mx0, __shfl_xor_sync(0xffffffffu, mx0, 2));
        mx1 = fmaxf(mx1, __shfl_xor_sync(0xffffffffu, mx1, 1));
        mx1 = fmaxf(mx1, __shfl_xor_sync(0xffffffffu, mx1, 2));
        float mnew0 = fmaxf(m0, mx0);
        float mnew1 = fmaxf(m1, mx1);
        float corr0 = __expf(m0 - mnew0);
        float corr1 = __expf(m1 - mnew1);
        m0 = mnew0; m1 = mnew1;

        uint32_t pH0[8], pL0[8], pH1[8], pL1[8];
        float sum0 = 0.f, sum1 = 0.f;
#pragma unroll
        for (int nt = 0; nt < 8; nt++) {
            float p00 = __expf(sc[nt][0] - mnew0);
            float p01 = __expf(sc[nt][1] - mnew0);
            float p10 = __expf(sc[nt][2] - mnew1);
            float p11 = __expf(sc[nt][3] - mnew1);
            sum0 += p00 + p01;
            sum1 += p10 + p11;
            split2(p00, p01, pH0[nt], pL0[nt]);
            split2(p10, p11, pH1[nt], pL1[nt]);
        }
        sum0 += __shfl_xor_sync(0xffffffffu, sum0, 1);
        sum0 += __shfl_xor_sync(0xffffffffu, sum0, 2);
        sum1 += __shfl_xor_sync(0xffffffffu, sum1, 1);
        sum1 += __shfl_xor_sync(0xffffffffu, sum1, 2);
        l0 = l0 * corr0 + sum0;
        l1 = l1 * corr1 + sum1;

#pragma unroll
        for (int nt = 0; nt < 16; nt++) {
            oc[nt][0] *= corr0; oc[nt][1] *= corr0;
            oc[nt][2] *= corr1; oc[nt][3] *= corr1;
        }

        // ---- O += P V (P A-frags straight from registers) ----
#pragma unroll
        for (int j = 0; j < 4; j++) {
            uint32_t ah[4] = { pH0[2 * j], pH1[2 * j], pH0[2 * j + 1], pH1[2 * j + 1] };
            uint32_t al[4] = { pL0[2 * j], pL1[2 * j], pL0[2 * j + 1], pL1[2 * j + 1] };
#pragma unroll
            for (int vj = 0; vj < 8; vj++) {
                uint32_t vh4[4], vl4[4];
                ldsm_x4_t(vh4, smb + sbase + 2 * PLN * 2 + voff_rel[vj] + j * 16 * VSTR * 2);
                ldsm_x4_t(vl4, smb + sbase + 3 * PLN * 2 + voff_rel[vj] + j * 16 * VSTR * 2);
#pragma unroll
                for (int hh = 0; hh < 2; hh++) {
                    const int nt = 2 * vj + hh;
                    mma_f16(oc[nt], ah, &vh4[2 * hh]);
                    mma_f16(oc[nt], al, &vh4[2 * hh]);
                    mma_f16(oc[nt], ah, &vl4[2 * hh]);
                }
            }
        }
        if (++s >= 3) s -= 3;
    }

    float linv0 = 1.f / l0;
    float linv1 = 1.f / l1;
    __half* Og = g_Oh + ((long)(b * TSEQ + q0)) * DIMC + h * DH;
#pragma unroll
    for (int nt = 0; nt < 16; nt++) {
        int c = nt * 8 + 2 * t;
        *(__half2*)&Og[(long)r0 * DIMC + c] =
            __floats2half2_rn(oc[nt][0] * linv0, oc[nt][1] * linv0);
        *(__half2*)&Og[(long)(r0 + 8) * DIMC + c] =
            __floats2half2_rn(oc[nt][2] * linv1, oc[nt][3] * linv1);
    }
}

// =====================================================================
// launch
// =====================================================================
extern "C" void kernel_launch(void* const* d_in, const int* in_sizes, int n_in,
                              void* d_out, int out_size) {
    const float* X  = (const float*)d_in[0];
    const float* Wq = (const float*)d_in[1];
    const float* Wk = (const float*)d_in[2];
    const float* Wv = (const float*)d_in[3];
    const float* Wo = (const float*)d_in[4];
    float* out = (float*)d_out;

    float  *QKVp;
    __half *Xh, *Wh, *Woh, *Oh;
    cudaGetSymbolAddress((void**)&QKVp, g_QKV);
    cudaGetSymbolAddress((void**)&Xh,  g_Xh);
    cudaGetSymbolAddress((void**)&Wh,  g_Wh);
    cudaGetSymbolAddress((void**)&Woh, g_Woh);
    cudaGetSymbolAddress((void**)&Oh,  g_Oh);

    cudaFuncSetAttribute(gemm_f16, cudaFuncAttributeMaxDynamicSharedMemorySize,
                         GEMM_SMEM_BYTES);
    cudaFuncSetAttribute(flash_tc, cudaFuncAttributeMaxDynamicSharedMemorySize,
                         FLASH_BYTES);

    rope_table<<<(TSEQ * 64 + 255) / 256, 256>>>();

    {
        int n4x = (BT * DIMC) / 4;
        pack_w<<<(n4x + 255) / 256, 256>>>(X, Xh, DIMC, 0, DIMC, n4x);
        int n4q = (DIMC * DIMC) / 4;
        pack_w<<<(n4q + 255) / 256, 256>>>(Wq, Wh, DIMC, 0, QKVN, n4q);
        int n4k = (DIMC * 1024) / 4;
        pack_w<<<(n4k + 255) / 256, 256>>>(Wk, Wh, 1024, KOFF, QKVN, n4k);
        pack_w<<<(n4k + 255) / 256, 256>>>(Wv, Wh, 1024, VOFF, QKVN, n4k);
        pack_w<<<(n4q + 255) / 256, 256>>>(Wo, Woh, DIMC, 0, DIMC, n4q);
    }

    gemm_f16<<<dim3(QKVN / 128, BT / 128), 256, GEMM_SMEM_BYTES>>>(Xh, Wh, QKVp, BT, QKVN, DIMC);

    {
        int total = BT * 8 * 16;
        split_kv<<<(total + 255) / 256, 256>>>(total);
    }

    flash_tc<<<dim3(TSEQ / 128, BB * NH), 256, FLASH_BYTES>>>();

    gemm_f16<<<dim3(DIMC / 128, BT / 128), 256, GEMM_SMEM_BYTES>>>(Oh, Woh, out, BT, DIMC, DIMC);
}